// round 1
// baseline (speedup 1.0000x reference)
#include <cuda_runtime.h>
#include <cuda_bf16.h>
#include <math.h>

// ---------------- problem constants ----------------
#define LL    2048      // total sequence (txt 512 + img 1536)
#define LTXT  512
#define LIMG  1536
#define DIM   3072
#define NH    24
#define DH    128
#define MLPD  12288

// ---------------- scratch (device globals; no allocs allowed) ----------------
__device__ float g_xmod  [(size_t)LL * DIM];
__device__ float g_qkv   [(size_t)LL * 3 * DIM];
__device__ float g_q     [(size_t)NH * LL * DH];
__device__ float g_k     [(size_t)NH * LL * DH];
__device__ float g_v     [(size_t)NH * LL * DH];
__device__ float g_scores[(size_t)NH * LL * LL];
__device__ float g_attn  [(size_t)LL * DIM];
__device__ float g_proj  [(size_t)LL * DIM];
__device__ float g_resid [(size_t)LL * DIM];
__device__ float g_mlpin [(size_t)LL * DIM];
__device__ float g_mlph  [(size_t)LL * MLPD];
__device__ float g_mlpout[(size_t)LL * DIM];

// ---------------- reductions ----------------
template<int NW>
__device__ __forceinline__ float blk_sum(float v, float* sh) {
    #pragma unroll
    for (int o = 16; o; o >>= 1) v += __shfl_down_sync(0xffffffffu, v, o);
    int lane = threadIdx.x & 31, w = threadIdx.x >> 5;
    if (lane == 0) sh[w] = v;
    __syncthreads();
    if (threadIdx.x == 0) {
        float r = 0.f;
        #pragma unroll
        for (int i = 0; i < NW; i++) r += sh[i];
        sh[0] = r;
    }
    __syncthreads();
    float r = sh[0];
    __syncthreads();
    return r;
}

template<int NW>
__device__ __forceinline__ float blk_max(float v, float* sh) {
    #pragma unroll
    for (int o = 16; o; o >>= 1) v = fmaxf(v, __shfl_down_sync(0xffffffffu, v, o));
    int lane = threadIdx.x & 31, w = threadIdx.x >> 5;
    if (lane == 0) sh[w] = v;
    __syncthreads();
    if (threadIdx.x == 0) {
        float r = sh[0];
        #pragma unroll
        for (int i = 1; i < NW; i++) r = fmaxf(r, sh[i]);
        sh[0] = r;
    }
    __syncthreads();
    float r = sh[0];
    __syncthreads();
    return r;
}

// ---------------- generic tiled fp32 GEMM: C = alpha * A @ op(B) + bias ----------------
// A: [M,K] row-major (lda). TRANSB ? B:[N,K] (ldb over K) : B:[K,N] (ldb over N).
// ACT: 0=none, 1=gelu(tanh). Batched via blockIdx.z with element strides sA,sB,sC.
// Requires: M%64==0, N%64==0, K%16==0, all pointers/lds 16B-granular. (Holds for all uses.)
template<bool TRANSB, int ACT>
__global__ __launch_bounds__(256)
void gemm_kernel(const float* __restrict__ A, const float* __restrict__ B,
                 float* __restrict__ C, const float* __restrict__ bias,
                 int M, int N, int K, int lda, int ldb, int ldc,
                 long long sA, long long sB, long long sC, float alpha)
{
    __shared__ __align__(16) float As[16][68];
    __shared__ __align__(16) float Bs[16][68];
    A += sA * blockIdx.z;
    B += sB * blockIdx.z;
    C += sC * blockIdx.z;
    const int m0 = blockIdx.y * 64;
    const int n0 = blockIdx.x * 64;
    const int tid = threadIdx.x;
    const int tx = tid & 15;
    const int ty = tid >> 4;
    const int lrow = tid >> 2;         // 0..63
    const int lk4  = (tid & 3) << 2;   // 0,4,8,12
    const int bkk  = tid >> 4;         // 0..15 (NN path)
    const int bn4  = (tid & 15) << 2;  // 0..60 (NN path)

    float acc[4][4] = {};

    for (int k0 = 0; k0 < K; k0 += 16) {
        float4 av = *reinterpret_cast<const float4*>(
            &A[(long long)(m0 + lrow) * lda + k0 + lk4]);
        As[lk4 + 0][lrow] = av.x; As[lk4 + 1][lrow] = av.y;
        As[lk4 + 2][lrow] = av.z; As[lk4 + 3][lrow] = av.w;
        if (TRANSB) {
            float4 bv = *reinterpret_cast<const float4*>(
                &B[(long long)(n0 + lrow) * ldb + k0 + lk4]);
            Bs[lk4 + 0][lrow] = bv.x; Bs[lk4 + 1][lrow] = bv.y;
            Bs[lk4 + 2][lrow] = bv.z; Bs[lk4 + 3][lrow] = bv.w;
        } else {
            float4 bv = *reinterpret_cast<const float4*>(
                &B[(long long)(k0 + bkk) * ldb + n0 + bn4]);
            Bs[bkk][bn4 + 0] = bv.x; Bs[bkk][bn4 + 1] = bv.y;
            Bs[bkk][bn4 + 2] = bv.z; Bs[bkk][bn4 + 3] = bv.w;
        }
        __syncthreads();
        #pragma unroll
        for (int kk = 0; kk < 16; kk++) {
            float4 a = *reinterpret_cast<const float4*>(&As[kk][ty << 2]);
            float4 b = *reinterpret_cast<const float4*>(&Bs[kk][tx << 2]);
            acc[0][0] += a.x * b.x; acc[0][1] += a.x * b.y;
            acc[0][2] += a.x * b.z; acc[0][3] += a.x * b.w;
            acc[1][0] += a.y * b.x; acc[1][1] += a.y * b.y;
            acc[1][2] += a.y * b.z; acc[1][3] += a.y * b.w;
            acc[2][0] += a.z * b.x; acc[2][1] += a.z * b.y;
            acc[2][2] += a.z * b.z; acc[2][3] += a.z * b.w;
            acc[3][0] += a.w * b.x; acc[3][1] += a.w * b.y;
            acc[3][2] += a.w * b.z; acc[3][3] += a.w * b.w;
        }
        __syncthreads();
    }

    #pragma unroll
    for (int i = 0; i < 4; i++) {
        const int m = m0 + (ty << 2) + i;
        #pragma unroll
        for (int j = 0; j < 4; j++) {
            const int n = n0 + (tx << 2) + j;
            float v = acc[i][j] * alpha;
            if (bias) v += bias[n];
            if (ACT == 1) {
                float x = v;
                v = 0.5f * x * (1.f + tanhf(0.7978845608028654f * (x + 0.044715f * x * x * x)));
            }
            C[(long long)m * ldc + n] = v;
        }
    }
}

// ---------------- LN + adaLN modulation (attention stage) ----------------
__global__ __launch_bounds__(256)
void lnmod_attn_kernel(const float* __restrict__ img_e, const float* __restrict__ txt_e,
                       const float* __restrict__ i_sc, const float* __restrict__ i_sh,
                       const float* __restrict__ t_sc, const float* __restrict__ t_sh,
                       float* __restrict__ out)
{
    const int row = blockIdx.x;
    const bool is_txt = row < LTXT;
    const float* x  = is_txt ? txt_e + (size_t)row * DIM : img_e + (size_t)(row - LTXT) * DIM;
    const float* sc = is_txt ? t_sc : i_sc;
    const float* sh = is_txt ? t_sh : i_sh;
    __shared__ float red[8];
    const int tid = threadIdx.x;
    float v[12];
    float s = 0.f, ss = 0.f;
    #pragma unroll
    for (int i = 0; i < 12; i++) {
        float a = x[tid + i * 256];
        v[i] = a; s += a; ss += a * a;
    }
    s  = blk_sum<8>(s,  red);
    ss = blk_sum<8>(ss, red);
    const float m   = s * (1.f / DIM);
    const float var = ss * (1.f / DIM) - m * m;
    const float rs  = rsqrtf(var + 1e-6f);
    #pragma unroll
    for (int i = 0; i < 12; i++) {
        const int c = tid + i * 256;
        out[(size_t)row * DIM + c] = (1.f + sc[c]) * (v[i] - m) * rs + sh[c];
    }
}

// ---------------- qkv split + RMSNorm(q,k) + RoPE ----------------
__global__ __launch_bounds__(128)
void qkv_post_kernel(const float* __restrict__ qkv, const float* __restrict__ pe,
                     const float* __restrict__ img_w, const float* __restrict__ txt_w,
                     float* __restrict__ q, float* __restrict__ k, float* __restrict__ v)
{
    const int row = blockIdx.x;   // global position 0..2047 (txt first)
    const int h   = blockIdx.y;
    const int d   = threadIdx.x;  // 0..127
    const float* w = (row < LTXT) ? txt_w : img_w;

    const size_t base = (size_t)row * (3 * DIM) + (size_t)h * DH + d;
    const float qv = qkv[base];
    const float kv = qkv[base + DIM];
    const float vv = qkv[base + 2 * DIM];

    __shared__ float shq[4], shk[4], bc[2];
    __shared__ float qn[DH], kn[DH];

    float qs = qv * qv, ks = kv * kv;
    #pragma unroll
    for (int o = 16; o; o >>= 1) {
        qs += __shfl_down_sync(0xffffffffu, qs, o);
        ks += __shfl_down_sync(0xffffffffu, ks, o);
    }
    const int lane = d & 31, wp = d >> 5;
    if (lane == 0) { shq[wp] = qs; shk[wp] = ks; }
    __syncthreads();
    if (d == 0) bc[0] = rsqrtf((shq[0] + shq[1] + shq[2] + shq[3]) * (1.f / DH) + 1e-6f);
    if (d == 1) bc[1] = rsqrtf((shk[0] + shk[1] + shk[2] + shk[3]) * (1.f / DH) + 1e-6f);
    __syncthreads();

    qn[d] = qv * bc[0] * w[d];
    kn[d] = kv * bc[1] * w[d];
    __syncthreads();

    const int d2 = d >> 1;
    const float c = pe[(size_t)row * 256 + d2 * 4 + 0];
    const float s = pe[(size_t)row * 256 + d2 * 4 + 2];
    const float qr = qn[d2 * 2], qi = qn[d2 * 2 + 1];
    const float kr = kn[d2 * 2], ki = kn[d2 * 2 + 1];
    const float qo = (d & 1) ? (qr * s + qi * c) : (qr * c - qi * s);
    const float ko = (d & 1) ? (kr * s + ki * c) : (kr * c - ki * s);

    const size_t o = ((size_t)h * LL + row) * DH + d;
    q[o] = qo; k[o] = ko; v[o] = vv;
}

// ---------------- row softmax (mask is all-true for this problem) ----------------
__global__ __launch_bounds__(256)
void softmax_kernel(float* __restrict__ s)
{
    float* p = s + (size_t)blockIdx.x * LL;
    const int tid = threadIdx.x;
    __shared__ float red[8];
    float v[8];
    float mx = -1e30f;
    #pragma unroll
    for (int i = 0; i < 8; i++) { v[i] = p[tid + i * 256]; mx = fmaxf(mx, v[i]); }
    mx = blk_max<8>(mx, red);
    float sum = 0.f;
    #pragma unroll
    for (int i = 0; i < 8; i++) { v[i] = expf(v[i] - mx); sum += v[i]; }
    sum = blk_sum<8>(sum, red);
    const float inv = 1.f / sum;
    #pragma unroll
    for (int i = 0; i < 8; i++) p[tid + i * 256] = v[i] * inv;
}

// ---------------- attn residual (gated) + LN + MLP modulation ----------------
__global__ __launch_bounds__(256)
void resid_lnmod_kernel(const float* __restrict__ proj,
                        const float* __restrict__ img_e, const float* __restrict__ txt_e,
                        const float* __restrict__ i_gate, const float* __restrict__ t_gate,
                        const float* __restrict__ i_sc, const float* __restrict__ i_sh,
                        const float* __restrict__ t_sc, const float* __restrict__ t_sh,
                        float* __restrict__ resid, float* __restrict__ mlpin)
{
    const int row = blockIdx.x;
    const bool is_txt = row < LTXT;
    const float* e  = is_txt ? txt_e + (size_t)row * DIM : img_e + (size_t)(row - LTXT) * DIM;
    const float* g  = is_txt ? t_gate : i_gate;
    const float* sc = is_txt ? t_sc : i_sc;
    const float* sh = is_txt ? t_sh : i_sh;
    __shared__ float red[8];
    const int tid = threadIdx.x;
    float r[12];
    float s = 0.f, ss = 0.f;
    #pragma unroll
    for (int i = 0; i < 12; i++) {
        const int c = tid + i * 256;
        float x = e[c] + g[c] * proj[(size_t)row * DIM + c];
        r[i] = x; s += x; ss += x * x;
        resid[(size_t)row * DIM + c] = x;
    }
    s  = blk_sum<8>(s,  red);
    ss = blk_sum<8>(ss, red);
    const float m   = s * (1.f / DIM);
    const float var = ss * (1.f / DIM) - m * m;
    const float rs  = rsqrtf(var + 1e-6f);
    #pragma unroll
    for (int i = 0; i < 12; i++) {
        const int c = tid + i * 256;
        mlpin[(size_t)row * DIM + c] = (1.f + sc[c]) * (r[i] - m) * rs + sh[c];
    }
}

// ---------------- final gated residual -> d_out (img first, then txt) ----------------
__global__ __launch_bounds__(256)
void final_kernel(const float* __restrict__ mlpout, const float* __restrict__ resid,
                  const float* __restrict__ i_gate, const float* __restrict__ t_gate,
                  float* __restrict__ out)
{
    const int row = blockIdx.x;
    const int tid = threadIdx.x;
    const bool is_txt = row < LTXT;
    const float* g = is_txt ? t_gate : i_gate;
    float* dst = is_txt ? out + (size_t)LIMG * DIM + (size_t)row * DIM
                        : out + (size_t)(row - LTXT) * DIM;
    #pragma unroll
    for (int i = 0; i < 12; i++) {
        const int c = tid + i * 256;
        dst[c] = resid[(size_t)row * DIM + c] + g[c] * mlpout[(size_t)row * DIM + c];
    }
}

// ---------------- launch ----------------
extern "C" void kernel_launch(void* const* d_in, const int* in_sizes, int n_in,
                              void* d_out, int out_size)
{
    const float* img_e       = (const float*)d_in[0];
    const float* txt_e       = (const float*)d_in[1];
    const float* pe          = (const float*)d_in[2];
    const float* i_attn_sc   = (const float*)d_in[3];
    const float* i_attn_sh   = (const float*)d_in[4];
    const float* i_attn_gate = (const float*)d_in[5];
    const float* i_mlp_sc    = (const float*)d_in[6];
    const float* i_mlp_sh    = (const float*)d_in[7];
    const float* i_mlp_gate  = (const float*)d_in[8];
    const float* t_attn_sc   = (const float*)d_in[9];
    const float* t_attn_sh   = (const float*)d_in[10];
    const float* t_attn_gate = (const float*)d_in[11];
    const float* t_mlp_sc    = (const float*)d_in[12];
    const float* t_mlp_sh    = (const float*)d_in[13];
    const float* t_mlp_gate  = (const float*)d_in[14];
    const float* i_qkv_w     = (const float*)d_in[15];
    const float* i_qkv_b     = (const float*)d_in[16];
    const float* i_qknorm    = (const float*)d_in[17];
    const float* t_qkv_w     = (const float*)d_in[18];
    const float* t_qkv_b     = (const float*)d_in[19];
    const float* t_qknorm    = (const float*)d_in[20];
    const float* proj_w      = (const float*)d_in[21];
    const float* proj_b      = (const float*)d_in[22];
    const float* i_mlp_w1    = (const float*)d_in[23];
    const float* i_mlp_b1    = (const float*)d_in[24];
    const float* i_mlp_w2    = (const float*)d_in[25];
    const float* i_mlp_b2    = (const float*)d_in[26];
    const float* t_mlp_w1    = (const float*)d_in[27];
    const float* t_mlp_b1    = (const float*)d_in[28];
    const float* t_mlp_w2    = (const float*)d_in[29];
    const float* t_mlp_b2    = (const float*)d_in[30];
    // d_in[31] = mask: all-true for this problem, intentionally unused.

    float *xmod, *qkv, *q, *k, *v, *sc, *attn, *proj, *resid, *mlpin, *mlph, *mlpout;
    cudaGetSymbolAddress((void**)&xmod,   g_xmod);
    cudaGetSymbolAddress((void**)&qkv,    g_qkv);
    cudaGetSymbolAddress((void**)&q,      g_q);
    cudaGetSymbolAddress((void**)&k,      g_k);
    cudaGetSymbolAddress((void**)&v,      g_v);
    cudaGetSymbolAddress((void**)&sc,     g_scores);
    cudaGetSymbolAddress((void**)&attn,   g_attn);
    cudaGetSymbolAddress((void**)&proj,   g_proj);
    cudaGetSymbolAddress((void**)&resid,  g_resid);
    cudaGetSymbolAddress((void**)&mlpin,  g_mlpin);
    cudaGetSymbolAddress((void**)&mlph,   g_mlph);
    cudaGetSymbolAddress((void**)&mlpout, g_mlpout);

    const float attn_scale = 0.08838834764831845f;  // 1/sqrt(128)

    // 1) LN + attention modulation (txt rows 0..511, img rows 512..2047)
    lnmod_attn_kernel<<<LL, 256>>>(img_e, txt_e, i_attn_sc, i_attn_sh, t_attn_sc, t_attn_sh, xmod);

    // 2) QKV GEMMs (per stream, distinct weights)
    gemm_kernel<true, 0><<<dim3(3 * DIM / 64, LTXT / 64, 1), 256>>>(
        xmod, t_qkv_w, qkv, t_qkv_b,
        LTXT, 3 * DIM, DIM, DIM, DIM, 3 * DIM, 0, 0, 0, 1.f);
    gemm_kernel<true, 0><<<dim3(3 * DIM / 64, LIMG / 64, 1), 256>>>(
        xmod + (size_t)LTXT * DIM, i_qkv_w, qkv + (size_t)LTXT * 3 * DIM, i_qkv_b,
        LIMG, 3 * DIM, DIM, DIM, DIM, 3 * DIM, 0, 0, 0, 1.f);

    // 3) split + RMSNorm + RoPE -> [H, L, DH]
    qkv_post_kernel<<<dim3(LL, NH), 128>>>(qkv, pe, i_qknorm, t_qknorm, q, k, v);

    // 4) scores = scale * q @ k^T  (batched over heads)
    gemm_kernel<true, 0><<<dim3(LL / 64, LL / 64, NH), 256>>>(
        q, k, sc, nullptr,
        LL, LL, DH, DH, DH, LL,
        (long long)LL * DH, (long long)LL * DH, (long long)LL * LL, attn_scale);

    // 5) softmax rows
    softmax_kernel<<<NH * LL, 256>>>(sc);

    // 6) o = attn @ v, written directly into [L, H*DH] layout
    gemm_kernel<false, 0><<<dim3(DH / 64, LL / 64, NH), 256>>>(
        sc, v, attn, nullptr,
        LL, DH, LL, LL, DH, DIM,
        (long long)LL * LL, (long long)LL * DH, (long long)DH, 1.f);

    // 7) shared projection
    gemm_kernel<true, 0><<<dim3(DIM / 64, LL / 64, 1), 256>>>(
        attn, proj_w, proj, proj_b,
        LL, DIM, DIM, DIM, DIM, DIM, 0, 0, 0, 1.f);

    // 8) gated attn residual + LN + MLP modulation
    resid_lnmod_kernel<<<LL, 256>>>(proj, img_e, txt_e,
                                    i_attn_gate, t_attn_gate,
                                    i_mlp_sc, i_mlp_sh, t_mlp_sc, t_mlp_sh,
                                    resid, mlpin);

    // 9) MLP up (gelu fused)
    gemm_kernel<true, 1><<<dim3(MLPD / 64, LTXT / 64, 1), 256>>>(
        mlpin, t_mlp_w1, mlph, t_mlp_b1,
        LTXT, MLPD, DIM, DIM, DIM, MLPD, 0, 0, 0, 1.f);
    gemm_kernel<true, 1><<<dim3(MLPD / 64, LIMG / 64, 1), 256>>>(
        mlpin + (size_t)LTXT * DIM, i_mlp_w1, mlph + (size_t)LTXT * MLPD, i_mlp_b1,
        LIMG, MLPD, DIM, DIM, DIM, MLPD, 0, 0, 0, 1.f);

    // 10) MLP down
    gemm_kernel<true, 0><<<dim3(DIM / 64, LTXT / 64, 1), 256>>>(
        mlph, t_mlp_w2, mlpout, t_mlp_b2,
        LTXT, DIM, MLPD, MLPD, MLPD, DIM, 0, 0, 0, 1.f);
    gemm_kernel<true, 0><<<dim3(DIM / 64, LIMG / 64, 1), 256>>>(
        mlph + (size_t)LTXT * MLPD, i_mlp_w2, mlpout + (size_t)LTXT * DIM, i_mlp_b2,
        LIMG, DIM, MLPD, MLPD, MLPD, DIM, 0, 0, 0, 1.f);

    // 11) final gated residual -> output (img block first, then txt block)
    final_kernel<<<LL, 256>>>(mlpout, resid, i_mlp_gate, t_mlp_gate, (float*)d_out);
}

// round 4
// speedup vs baseline: 2.5772x; 2.5772x over previous
#include <cuda_runtime.h>
#include <cuda_bf16.h>
#include <stdint.h>
#include <math.h>

// ---------------- problem constants ----------------
#define LL    2048
#define LTXT  512
#define LIMG  1536
#define DIM   3072
#define NH    24
#define DH    128
#define MLPD  12288

// ---------------- scratch ----------------
__device__ float g_xmod  [(size_t)LL * DIM];
__device__ float g_qkv   [(size_t)LL * 3 * DIM];
__device__ float g_q     [(size_t)NH * LL * DH];
__device__ float g_k     [(size_t)NH * LL * DH];
__device__ float g_v     [(size_t)NH * LL * DH];
__device__ float g_scores[(size_t)NH * LL * LL];
__device__ float g_attn  [(size_t)LL * DIM];
__device__ float g_proj  [(size_t)LL * DIM];
__device__ float g_resid [(size_t)LL * DIM];
__device__ float g_mlpin [(size_t)LL * DIM];
__device__ float g_mlph  [(size_t)LL * MLPD];
__device__ float g_mlpout[(size_t)LL * DIM];

// ---------------- reductions ----------------
template<int NW>
__device__ __forceinline__ float blk_sum(float v, float* sh) {
    #pragma unroll
    for (int o = 16; o; o >>= 1) v += __shfl_down_sync(0xffffffffu, v, o);
    int lane = threadIdx.x & 31, w = threadIdx.x >> 5;
    if (lane == 0) sh[w] = v;
    __syncthreads();
    if (threadIdx.x == 0) {
        float r = 0.f;
        #pragma unroll
        for (int i = 0; i < NW; i++) r += sh[i];
        sh[0] = r;
    }
    __syncthreads();
    float r = sh[0];
    __syncthreads();
    return r;
}

template<int NW>
__device__ __forceinline__ float blk_max(float v, float* sh) {
    #pragma unroll
    for (int o = 16; o; o >>= 1) v = fmaxf(v, __shfl_down_sync(0xffffffffu, v, o));
    int lane = threadIdx.x & 31, w = threadIdx.x >> 5;
    if (lane == 0) sh[w] = v;
    __syncthreads();
    if (threadIdx.x == 0) {
        float r = sh[0];
        #pragma unroll
        for (int i = 1; i < NW; i++) r = fmaxf(r, sh[i]);
        sh[0] = r;
    }
    __syncthreads();
    float r = sh[0];
    __syncthreads();
    return r;
}

// ---------------- tensor-core primitives ----------------
__device__ __forceinline__ void mma_bf16(float d[4], const uint32_t a[4],
                                         const uint32_t b[2]) {
    asm volatile(
        "mma.sync.aligned.m16n8k16.row.col.f32.bf16.bf16.f32 "
        "{%0,%1,%2,%3},{%4,%5,%6,%7},{%8,%9},{%0,%1,%2,%3};"
        : "+f"(d[0]), "+f"(d[1]), "+f"(d[2]), "+f"(d[3])
        : "r"(a[0]), "r"(a[1]), "r"(a[2]), "r"(a[3]), "r"(b[0]), "r"(b[1]));
}

__device__ __forceinline__ void ldsm4(uint32_t r[4], uint32_t addr) {
    asm volatile("ldmatrix.sync.aligned.m8n8.x4.shared.b16 {%0,%1,%2,%3}, [%4];"
                 : "=r"(r[0]), "=r"(r[1]), "=r"(r[2]), "=r"(r[3]) : "r"(addr));
}

__device__ __forceinline__ void ldsm2(uint32_t r[2], uint32_t addr) {
    asm volatile("ldmatrix.sync.aligned.m8n8.x2.shared.b16 {%0,%1}, [%2];"
                 : "=r"(r[0]), "=r"(r[1]) : "r"(addr));
}

__device__ __forceinline__ void split_store4(__nv_bfloat16* hi, __nv_bfloat16* lo,
                                             float4 v) {
    __nv_bfloat16 h0 = __float2bfloat16(v.x);
    __nv_bfloat16 h1 = __float2bfloat16(v.y);
    __nv_bfloat16 h2 = __float2bfloat16(v.z);
    __nv_bfloat16 h3 = __float2bfloat16(v.w);
    __nv_bfloat16 l0 = __float2bfloat16(v.x - __bfloat162float(h0));
    __nv_bfloat16 l1 = __float2bfloat16(v.y - __bfloat162float(h1));
    __nv_bfloat16 l2 = __float2bfloat16(v.z - __bfloat162float(h2));
    __nv_bfloat16 l3 = __float2bfloat16(v.w - __bfloat162float(h3));
    *reinterpret_cast<__nv_bfloat162*>(hi)     = __nv_bfloat162(h0, h1);
    *reinterpret_cast<__nv_bfloat162*>(hi + 2) = __nv_bfloat162(h2, h3);
    *reinterpret_cast<__nv_bfloat162*>(lo)     = __nv_bfloat162(l0, l1);
    *reinterpret_cast<__nv_bfloat162*>(lo + 2) = __nv_bfloat162(l2, l3);
}

// ---------------- staging helpers ----------------
template<bool TRANSB>
__device__ __forceinline__ void g2r(const float* __restrict__ A,
                                    const float* __restrict__ B,
                                    int tid, int m0, int n0, int lda, int ldb,
                                    int k0, float4 ra[4], float4 rb[4]) {
    #pragma unroll
    for (int i = 0; i < 4; i++) {
        int f = tid + i * 256;
        int row = f >> 3, kc = (f & 7) << 2;
        ra[i] = *reinterpret_cast<const float4*>(
            &A[(long long)(m0 + row) * lda + k0 + kc]);
    }
    #pragma unroll
    for (int i = 0; i < 4; i++) {
        int f = tid + i * 256;
        if (TRANSB) {
            int row = f >> 3, kc = (f & 7) << 2;
            rb[i] = *reinterpret_cast<const float4*>(
                &B[(long long)(n0 + row) * ldb + k0 + kc]);
        } else {
            int k = f >> 5, n4 = (f & 31) << 2;
            rb[i] = *reinterpret_cast<const float4*>(
                &B[(long long)(k0 + k) * ldb + n0 + n4]);
        }
    }
}

template<bool TRANSB>
__device__ __forceinline__ void r2s(__nv_bfloat16 (*As)[128][40],
                                    __nv_bfloat16 (*Bs)[128][40],
                                    int tid, const float4 ra[4], const float4 rb[4]) {
    #pragma unroll
    for (int i = 0; i < 4; i++) {
        int f = tid + i * 256;
        int row = f >> 3, kc = (f & 7) << 2;
        split_store4(&As[0][row][kc], &As[1][row][kc], ra[i]);
    }
    #pragma unroll
    for (int i = 0; i < 4; i++) {
        int f = tid + i * 256;
        if (TRANSB) {
            int row = f >> 3, kc = (f & 7) << 2;
            split_store4(&Bs[0][row][kc], &Bs[1][row][kc], rb[i]);
        } else {
            int k = f >> 5, n4 = (f & 31) << 2;
            float v[4];
            v[0] = rb[i].x; v[1] = rb[i].y; v[2] = rb[i].z; v[3] = rb[i].w;
            #pragma unroll
            for (int j = 0; j < 4; j++) {
                __nv_bfloat16 h = __float2bfloat16(v[j]);
                __nv_bfloat16 l = __float2bfloat16(v[j] - __bfloat162float(h));
                Bs[0][n4 + j][k] = h;
                Bs[1][n4 + j][k] = l;
            }
        }
    }
}

// ---------------- tensor-core GEMM (bf16 hi/lo split, fp32 accum) ----------------
// C = alpha * A @ op(B) (+bias) (+gelu). A:[M,K] rm. TRANSB ? B:[N,K] : B:[K,N].
// Block 128x128, KT=32. Requires M%128==0, N%128==0, K%32==0.
template<bool TRANSB, int ACT>
__global__ __launch_bounds__(256)
void gemm_tc(const float* __restrict__ A, const float* __restrict__ B,
             float* __restrict__ C, const float* __restrict__ bias,
             int M, int N, int K, int lda, int ldb, int ldc,
             long long sA, long long sB, long long sC, float alpha)
{
    __shared__ __align__(16) __nv_bfloat16 As[2][128][40];
    __shared__ __align__(16) __nv_bfloat16 Bs[2][128][40];

    A += sA * blockIdx.z;
    B += sB * blockIdx.z;
    C += sC * blockIdx.z;
    const int m0 = blockIdx.y * 128;
    const int n0 = blockIdx.x * 128;
    const int tid = threadIdx.x;
    const int lane = tid & 31;
    const int warp = tid >> 5;
    const int wm = (warp >> 2) * 64;
    const int wn = (warp & 3) * 32;

    float4 ra[4], rb[4];
    float acc[4][4][4];
    #pragma unroll
    for (int i = 0; i < 4; i++)
        #pragma unroll
        for (int j = 0; j < 4; j++) {
            acc[i][j][0] = 0.f; acc[i][j][1] = 0.f;
            acc[i][j][2] = 0.f; acc[i][j][3] = 0.f;
        }

    const uint32_t aBase = (uint32_t)__cvta_generic_to_shared(&As[0][0][0]);
    const uint32_t bBase = (uint32_t)__cvta_generic_to_shared(&Bs[0][0][0]);
    const uint32_t planeOff = 128u * 40u * 2u;

    const int aRowLane = lane & 15;
    const int aKLane   = (lane & 16) ? 8 : 0;
    const int bRowLane = lane & 7;
    const int bKLane   = (lane & 8) ? 8 : 0;

    g2r<TRANSB>(A, B, tid, m0, n0, lda, ldb, 0, ra, rb);
    r2s<TRANSB>(As, Bs, tid, ra, rb);
    __syncthreads();

    for (int k0 = 0; k0 < K; k0 += 32) {
        const bool more = (k0 + 32) < K;
        if (more) g2r<TRANSB>(A, B, tid, m0, n0, lda, ldb, k0 + 32, ra, rb);

        #pragma unroll
        for (int kh = 0; kh < 32; kh += 16) {
            uint32_t ah[4][4];
            uint32_t al[4][4];
            uint32_t bh[4][2];
            uint32_t bl[4][2];
            #pragma unroll
            for (int mt = 0; mt < 4; mt++) {
                uint32_t offA = (uint32_t)((wm + mt * 16 + aRowLane) * 40
                                           + kh + aKLane) * 2u;
                ldsm4(ah[mt], aBase + offA);
                ldsm4(al[mt], aBase + planeOff + offA);
            }
            #pragma unroll
            for (int nt = 0; nt < 4; nt++) {
                uint32_t offB = (uint32_t)((wn + nt * 8 + bRowLane) * 40
                                           + kh + bKLane) * 2u;
                ldsm2(bh[nt], bBase + offB);
                ldsm2(bl[nt], bBase + planeOff + offB);
            }
            #pragma unroll
            for (int mt = 0; mt < 4; mt++)
                #pragma unroll
                for (int nt = 0; nt < 4; nt++) {
                    mma_bf16(acc[mt][nt], ah[mt], bh[nt]);
                    mma_bf16(acc[mt][nt], ah[mt], bl[nt]);
                    mma_bf16(acc[mt][nt], al[mt], bh[nt]);
                }
        }

        __syncthreads();
        if (more) {
            r2s<TRANSB>(As, Bs, tid, ra, rb);
            __syncthreads();
        }
    }

    // epilogue
    const int crow = lane >> 2;
    const int ccol = (lane & 3) << 1;
    #pragma unroll
    for (int mt = 0; mt < 4; mt++) {
        #pragma unroll
        for (int nt = 0; nt < 4; nt++) {
            const int gn = n0 + wn + nt * 8 + ccol;
            #pragma unroll
            for (int half = 0; half < 2; half++) {
                const int gm = m0 + wm + mt * 16 + crow + half * 8;
                float v0 = acc[mt][nt][half * 2 + 0] * alpha;
                float v1 = acc[mt][nt][half * 2 + 1] * alpha;
                if (bias) { v0 += bias[gn]; v1 += bias[gn + 1]; }
                if (ACT == 1) {
                    float x = v0;
                    v0 = 0.5f * x * (1.f + tanhf(0.7978845608028654f *
                                                 (x + 0.044715f * x * x * x)));
                    x = v1;
                    v1 = 0.5f * x * (1.f + tanhf(0.7978845608028654f *
                                                 (x + 0.044715f * x * x * x)));
                }
                *reinterpret_cast<float2*>(&C[(long long)gm * ldc + gn]) =
                    make_float2(v0, v1);
            }
        }
    }
}

// ---------------- LN + adaLN modulation (attention stage) ----------------
__global__ __launch_bounds__(256)
void lnmod_attn_kernel(const float* __restrict__ img_e, const float* __restrict__ txt_e,
                       const float* __restrict__ i_sc, const float* __restrict__ i_sh,
                       const float* __restrict__ t_sc, const float* __restrict__ t_sh,
                       float* __restrict__ out)
{
    const int row = blockIdx.x;
    const bool is_txt = row < LTXT;
    const float* x  = is_txt ? txt_e + (size_t)row * DIM : img_e + (size_t)(row - LTXT) * DIM;
    const float* sc = is_txt ? t_sc : i_sc;
    const float* sh = is_txt ? t_sh : i_sh;
    __shared__ float red[8];
    const int tid = threadIdx.x;
    float v[12];
    float s = 0.f, ss = 0.f;
    #pragma unroll
    for (int i = 0; i < 12; i++) {
        float a = x[tid + i * 256];
        v[i] = a; s += a; ss += a * a;
    }
    s  = blk_sum<8>(s,  red);
    ss = blk_sum<8>(ss, red);
    const float m   = s * (1.f / DIM);
    const float var = ss * (1.f / DIM) - m * m;
    const float rs  = rsqrtf(var + 1e-6f);
    #pragma unroll
    for (int i = 0; i < 12; i++) {
        const int c = tid + i * 256;
        out[(size_t)row * DIM + c] = (1.f + sc[c]) * (v[i] - m) * rs + sh[c];
    }
}

// ---------------- qkv split + RMSNorm(q,k) + RoPE ----------------
__global__ __launch_bounds__(128)
void qkv_post_kernel(const float* __restrict__ qkv, const float* __restrict__ pe,
                     const float* __restrict__ img_w, const float* __restrict__ txt_w,
                     float* __restrict__ q, float* __restrict__ k, float* __restrict__ v)
{
    const int row = blockIdx.x;
    const int h   = blockIdx.y;
    const int d   = threadIdx.x;
    const float* w = (row < LTXT) ? txt_w : img_w;

    const size_t base = (size_t)row * (3 * DIM) + (size_t)h * DH + d;
    const float qv = qkv[base];
    const float kv = qkv[base + DIM];
    const float vv = qkv[base + 2 * DIM];

    __shared__ float shq[4], shk[4], bc[2];
    __shared__ float qn[DH], kn[DH];

    float qs = qv * qv, ks = kv * kv;
    #pragma unroll
    for (int o = 16; o; o >>= 1) {
        qs += __shfl_down_sync(0xffffffffu, qs, o);
        ks += __shfl_down_sync(0xffffffffu, ks, o);
    }
    const int lane = d & 31, wp = d >> 5;
    if (lane == 0) { shq[wp] = qs; shk[wp] = ks; }
    __syncthreads();
    if (d == 0) bc[0] = rsqrtf((shq[0] + shq[1] + shq[2] + shq[3]) * (1.f / DH) + 1e-6f);
    if (d == 1) bc[1] = rsqrtf((shk[0] + shk[1] + shk[2] + shk[3]) * (1.f / DH) + 1e-6f);
    __syncthreads();

    qn[d] = qv * bc[0] * w[d];
    kn[d] = kv * bc[1] * w[d];
    __syncthreads();

    const int d2 = d >> 1;
    const float c = pe[(size_t)row * 256 + d2 * 4 + 0];
    const float s = pe[(size_t)row * 256 + d2 * 4 + 2];
    const float qr = qn[d2 * 2], qi = qn[d2 * 2 + 1];
    const float kr = kn[d2 * 2], ki = kn[d2 * 2 + 1];
    const float qo = (d & 1) ? (qr * s + qi * c) : (qr * c - qi * s);
    const float ko = (d & 1) ? (kr * s + ki * c) : (kr * c - ki * s);

    const size_t o = ((size_t)h * LL + row) * DH + d;
    q[o] = qo; k[o] = ko; v[o] = vv;
}

// ---------------- row softmax ----------------
__global__ __launch_bounds__(256)
void softmax_kernel(float* __restrict__ s)
{
    float* p = s + (size_t)blockIdx.x * LL;
    const int tid = threadIdx.x;
    __shared__ float red[8];
    float v[8];
    float mx = -1e30f;
    #pragma unroll
    for (int i = 0; i < 8; i++) { v[i] = p[tid + i * 256]; mx = fmaxf(mx, v[i]); }
    mx = blk_max<8>(mx, red);
    float sum = 0.f;
    #pragma unroll
    for (int i = 0; i < 8; i++) { v[i] = expf(v[i] - mx); sum += v[i]; }
    sum = blk_sum<8>(sum, red);
    const float inv = 1.f / sum;
    #pragma unroll
    for (int i = 0; i < 8; i++) p[tid + i * 256] = v[i] * inv;
}

// ---------------- attn residual (gated) + LN + MLP modulation ----------------
__global__ __launch_bounds__(256)
void resid_lnmod_kernel(const float* __restrict__ proj,
                        const float* __restrict__ img_e, const float* __restrict__ txt_e,
                        const float* __restrict__ i_gate, const float* __restrict__ t_gate,
                        const float* __restrict__ i_sc, const float* __restrict__ i_sh,
                        const float* __restrict__ t_sc, const float* __restrict__ t_sh,
                        float* __restrict__ resid, float* __restrict__ mlpin)
{
    const int row = blockIdx.x;
    const bool is_txt = row < LTXT;
    const float* e  = is_txt ? txt_e + (size_t)row * DIM : img_e + (size_t)(row - LTXT) * DIM;
    const float* g  = is_txt ? t_gate : i_gate;
    const float* sc = is_txt ? t_sc : i_sc;
    const float* sh = is_txt ? t_sh : i_sh;
    __shared__ float red[8];
    const int tid = threadIdx.x;
    float r[12];
    float s = 0.f, ss = 0.f;
    #pragma unroll
    for (int i = 0; i < 12; i++) {
        const int c = tid + i * 256;
        float x = e[c] + g[c] * proj[(size_t)row * DIM + c];
        r[i] = x; s += x; ss += x * x;
        resid[(size_t)row * DIM + c] = x;
    }
    s  = blk_sum<8>(s,  red);
    ss = blk_sum<8>(ss, red);
    const float m   = s * (1.f / DIM);
    const float var = ss * (1.f / DIM) - m * m;
    const float rs  = rsqrtf(var + 1e-6f);
    #pragma unroll
    for (int i = 0; i < 12; i++) {
        const int c = tid + i * 256;
        mlpin[(size_t)row * DIM + c] = (1.f + sc[c]) * (r[i] - m) * rs + sh[c];
    }
}

// ---------------- final gated residual -> d_out ----------------
__global__ __launch_bounds__(256)
void final_kernel(const float* __restrict__ mlpout, const float* __restrict__ resid,
                  const float* __restrict__ i_gate, const float* __restrict__ t_gate,
                  float* __restrict__ out)
{
    const int row = blockIdx.x;
    const int tid = threadIdx.x;
    const bool is_txt = row < LTXT;
    const float* g = is_txt ? t_gate : i_gate;
    float* dst = is_txt ? out + (size_t)LIMG * DIM + (size_t)row * DIM
                        : out + (size_t)(row - LTXT) * DIM;
    #pragma unroll
    for (int i = 0; i < 12; i++) {
        const int c = tid + i * 256;
        dst[c] = resid[(size_t)row * DIM + c] + g[c] * mlpout[(size_t)row * DIM + c];
    }
}

// ---------------- launch ----------------
extern "C" void kernel_launch(void* const* d_in, const int* in_sizes, int n_in,
                              void* d_out, int out_size)
{
    const float* img_e       = (const float*)d_in[0];
    const float* txt_e       = (const float*)d_in[1];
    const float* pe          = (const float*)d_in[2];
    const float* i_attn_sc   = (const float*)d_in[3];
    const float* i_attn_sh   = (const float*)d_in[4];
    const float* i_attn_gate = (const float*)d_in[5];
    const float* i_mlp_sc    = (const float*)d_in[6];
    const float* i_mlp_sh    = (const float*)d_in[7];
    const float* i_mlp_gate  = (const float*)d_in[8];
    const float* t_attn_sc   = (const float*)d_in[9];
    const float* t_attn_sh   = (const float*)d_in[10];
    const float* t_attn_gate = (const float*)d_in[11];
    const float* t_mlp_sc    = (const float*)d_in[12];
    const float* t_mlp_sh    = (const float*)d_in[13];
    const float* t_mlp_gate  = (const float*)d_in[14];
    const float* i_qkv_w     = (const float*)d_in[15];
    const float* i_qkv_b     = (const float*)d_in[16];
    const float* i_qknorm    = (const float*)d_in[17];
    const float* t_qkv_w     = (const float*)d_in[18];
    const float* t_qkv_b     = (const float*)d_in[19];
    const float* t_qknorm    = (const float*)d_in[20];
    const float* proj_w      = (const float*)d_in[21];
    const float* proj_b      = (const float*)d_in[22];
    const float* i_mlp_w1    = (const float*)d_in[23];
    const float* i_mlp_b1    = (const float*)d_in[24];
    const float* i_mlp_w2    = (const float*)d_in[25];
    const float* i_mlp_b2    = (const float*)d_in[26];
    const float* t_mlp_w1    = (const float*)d_in[27];
    const float* t_mlp_b1    = (const float*)d_in[28];
    const float* t_mlp_w2    = (const float*)d_in[29];
    const float* t_mlp_b2    = (const float*)d_in[30];
    // d_in[31] = mask (all-true; unused)

    float *xmod, *qkv, *q, *k, *v, *sc, *attn, *proj, *resid, *mlpin, *mlph, *mlpout;
    cudaGetSymbolAddress((void**)&xmod,   g_xmod);
    cudaGetSymbolAddress((void**)&qkv,    g_qkv);
    cudaGetSymbolAddress((void**)&q,      g_q);
    cudaGetSymbolAddress((void**)&k,      g_k);
    cudaGetSymbolAddress((void**)&v,      g_v);
    cudaGetSymbolAddress((void**)&sc,     g_scores);
    cudaGetSymbolAddress((void**)&attn,   g_attn);
    cudaGetSymbolAddress((void**)&proj,   g_proj);
    cudaGetSymbolAddress((void**)&resid,  g_resid);
    cudaGetSymbolAddress((void**)&mlpin,  g_mlpin);
    cudaGetSymbolAddress((void**)&mlph,   g_mlph);
    cudaGetSymbolAddress((void**)&mlpout, g_mlpout);

    const float attn_scale = 0.08838834764831845f;  // 1/sqrt(128)

    // 1) LN + attention modulation
    lnmod_attn_kernel<<<LL, 256>>>(img_e, txt_e, i_attn_sc, i_attn_sh, t_attn_sc, t_attn_sh, xmod);

    // 2) QKV GEMMs
    gemm_tc<true, 0><<<dim3(3 * DIM / 128, LTXT / 128, 1), 256>>>(
        xmod, t_qkv_w, qkv, t_qkv_b,
        LTXT, 3 * DIM, DIM, DIM, DIM, 3 * DIM, 0, 0, 0, 1.f);
    gemm_tc<true, 0><<<dim3(3 * DIM / 128, LIMG / 128, 1), 256>>>(
        xmod + (size_t)LTXT * DIM, i_qkv_w, qkv + (size_t)LTXT * 3 * DIM, i_qkv_b,
        LIMG, 3 * DIM, DIM, DIM, DIM, 3 * DIM, 0, 0, 0, 1.f);

    // 3) split + RMSNorm + RoPE
    qkv_post_kernel<<<dim3(LL, NH), 128>>>(qkv, pe, i_qknorm, t_qknorm, q, k, v);

    // 4) scores = scale * q @ k^T
    gemm_tc<true, 0><<<dim3(LL / 128, LL / 128, NH), 256>>>(
        q, k, sc, nullptr,
        LL, LL, DH, DH, DH, LL,
        (long long)LL * DH, (long long)LL * DH, (long long)LL * LL, attn_scale);

    // 5) softmax
    softmax_kernel<<<NH * LL, 256>>>(sc);

    // 6) o = attn @ v
    gemm_tc<false, 0><<<dim3(DH / 128, LL / 128, NH), 256>>>(
        sc, v, attn, nullptr,
        LL, DH, LL, LL, DH, DIM,
        (long long)LL * LL, (long long)LL * DH, (long long)DH, 1.f);

    // 7) shared projection
    gemm_tc<true, 0><<<dim3(DIM / 128, LL / 128, 1), 256>>>(
        attn, proj_w, proj, proj_b,
        LL, DIM, DIM, DIM, DIM, DIM, 0, 0, 0, 1.f);

    // 8) gated attn residual + LN + MLP modulation
    resid_lnmod_kernel<<<LL, 256>>>(proj, img_e, txt_e,
                                    i_attn_gate, t_attn_gate,
                                    i_mlp_sc, i_mlp_sh, t_mlp_sc, t_mlp_sh,
                                    resid, mlpin);

    // 9) MLP up (gelu fused)
    gemm_tc<true, 1><<<dim3(MLPD / 128, LTXT / 128, 1), 256>>>(
        mlpin, t_mlp_w1, mlph, t_mlp_b1,
        LTXT, MLPD, DIM, DIM, DIM, MLPD, 0, 0, 0, 1.f);
    gemm_tc<true, 1><<<dim3(MLPD / 128, LIMG / 128, 1), 256>>>(
        mlpin + (size_t)LTXT * DIM, i_mlp_w1, mlph + (size_t)LTXT * MLPD, i_mlp_b1,
        LIMG, MLPD, DIM, DIM, DIM, MLPD, 0, 0, 0, 1.f);

    // 10) MLP down
    gemm_tc<true, 0><<<dim3(DIM / 128, LTXT / 128, 1), 256>>>(
        mlph, t_mlp_w2, mlpout, t_mlp_b2,
        LTXT, DIM, MLPD, MLPD, MLPD, DIM, 0, 0, 0, 1.f);
    gemm_tc<true, 0><<<dim3(DIM / 128, LIMG / 128, 1), 256>>>(
        mlph + (size_t)LTXT * MLPD, i_mlp_w2, mlpout + (size_t)LTXT * DIM, i_mlp_b2,
        LIMG, DIM, MLPD, MLPD, MLPD, DIM, 0, 0, 0, 1.f);

    // 11) final gated residual -> output
    final_kernel<<<LL, 256>>>(mlpout, resid, i_mlp_gate, t_mlp_gate, (float*)d_out);
}

// round 6
// speedup vs baseline: 2.6182x; 1.0159x over previous
#include <cuda_runtime.h>
#include <cuda_bf16.h>
#include <stdint.h>
#include <math.h>

// ---------------- problem constants ----------------
#define LL    2048
#define LTXT  512
#define LIMG  1536
#define DIM   3072
#define NH    24
#define DH    128
#define MLPD  12288

// weight plane offsets (elements)
#define W_TQKV 0LL
#define W_IQKV (W_TQKV + (long long)3*DIM*DIM)
#define W_PROJ (W_IQKV + (long long)3*DIM*DIM)
#define W_TW1  (W_PROJ + (long long)DIM*DIM)
#define W_IW1  (W_TW1  + (long long)MLPD*DIM)
#define W_TW2  (W_IW1  + (long long)MLPD*DIM)
#define W_IW2  (W_TW2  + (long long)DIM*MLPD)
#define W_TOT  (W_IW2  + (long long)DIM*MLPD)

// ---------------- scratch ----------------
__device__ __nv_bfloat16 g_wh [W_TOT];
__device__ __nv_bfloat16 g_wl [W_TOT];
__device__ __nv_bfloat16 g_xmh[(size_t)LL * DIM];
__device__ __nv_bfloat16 g_xml[(size_t)LL * DIM];
__device__ float         g_qkv[(size_t)LL * 3 * DIM];
__device__ __nv_bfloat16 g_qh [(size_t)NH * LL * DH];
__device__ __nv_bfloat16 g_ql [(size_t)NH * LL * DH];
__device__ __nv_bfloat16 g_kh [(size_t)NH * LL * DH];
__device__ __nv_bfloat16 g_kl [(size_t)NH * LL * DH];
__device__ __nv_bfloat16 g_vth[(size_t)NH * DH * LL];   // [h][dh][l]
__device__ __nv_bfloat16 g_vtl[(size_t)NH * DH * LL];
__device__ float         g_scores[(size_t)NH * LL * LL];
__device__ __nv_bfloat16 g_ph [(size_t)NH * LL * LL];
__device__ __nv_bfloat16 g_pl [(size_t)NH * LL * LL];
__device__ __nv_bfloat16 g_ath[(size_t)LL * DIM];
__device__ __nv_bfloat16 g_atl[(size_t)LL * DIM];
__device__ float         g_proj[(size_t)LL * DIM];
__device__ float         g_resid[(size_t)LL * DIM];
__device__ __nv_bfloat16 g_mih[(size_t)LL * DIM];
__device__ __nv_bfloat16 g_mil[(size_t)LL * DIM];
__device__ __nv_bfloat16 g_mhh[(size_t)LL * MLPD];
__device__ __nv_bfloat16 g_mhl[(size_t)LL * MLPD];
__device__ float         g_mlpout[(size_t)LL * DIM];

// ---------------- helpers ----------------
__device__ __forceinline__ void split1(float x, __nv_bfloat16& h, __nv_bfloat16& l) {
    h = __float2bfloat16(x);
    l = __float2bfloat16(x - __bfloat162float(h));
}

template<int NW>
__device__ __forceinline__ float blk_sum(float v, float* sh) {
    #pragma unroll
    for (int o = 16; o; o >>= 1) v += __shfl_down_sync(0xffffffffu, v, o);
    int lane = threadIdx.x & 31, w = threadIdx.x >> 5;
    if (lane == 0) sh[w] = v;
    __syncthreads();
    if (threadIdx.x == 0) {
        float r = 0.f;
        #pragma unroll
        for (int i = 0; i < NW; i++) r += sh[i];
        sh[0] = r;
    }
    __syncthreads();
    float r = sh[0];
    __syncthreads();
    return r;
}

template<int NW>
__device__ __forceinline__ float blk_max(float v, float* sh) {
    #pragma unroll
    for (int o = 16; o; o >>= 1) v = fmaxf(v, __shfl_down_sync(0xffffffffu, v, o));
    int lane = threadIdx.x & 31, w = threadIdx.x >> 5;
    if (lane == 0) sh[w] = v;
    __syncthreads();
    if (threadIdx.x == 0) {
        float r = sh[0];
        #pragma unroll
        for (int i = 1; i < NW; i++) r = fmaxf(r, sh[i]);
        sh[0] = r;
    }
    __syncthreads();
    float r = sh[0];
    __syncthreads();
    return r;
}

// ---------------- tensor-core primitives ----------------
__device__ __forceinline__ void mma_bf16(float d[4], const uint32_t a[4],
                                         const uint32_t b[2]) {
    asm volatile(
        "mma.sync.aligned.m16n8k16.row.col.f32.bf16.bf16.f32 "
        "{%0,%1,%2,%3},{%4,%5,%6,%7},{%8,%9},{%0,%1,%2,%3};"
        : "+f"(d[0]), "+f"(d[1]), "+f"(d[2]), "+f"(d[3])
        : "r"(a[0]), "r"(a[1]), "r"(a[2]), "r"(a[3]), "r"(b[0]), "r"(b[1]));
}

__device__ __forceinline__ void ldsm4(uint32_t r[4], uint32_t addr) {
    asm volatile("ldmatrix.sync.aligned.m8n8.x4.shared.b16 {%0,%1,%2,%3}, [%4];"
                 : "=r"(r[0]), "=r"(r[1]), "=r"(r[2]), "=r"(r[3]) : "r"(addr));
}

__device__ __forceinline__ void cpa(uint32_t d, const void* s) {
    asm volatile("cp.async.cg.shared.global [%0], [%1], 16;" :: "r"(d), "l"(s));
}

// ---------------- GEMM staging / compute ----------------
// smem stage layout: Ah[128][40], Al, Bh, Bl — 10240 B each, 40960 B per stage.
__device__ __forceinline__ void issue_tile(
    const __nv_bfloat16* __restrict__ Ah, const __nv_bfloat16* __restrict__ Al,
    const __nv_bfloat16* __restrict__ Bh, const __nv_bfloat16* __restrict__ Bl,
    int tid, int m0, int n0, int lda, int ldb, int k0, uint32_t sb)
{
    #pragma unroll
    for (int i = 0; i < 2; i++) {
        int s = tid + i * 256;
        int row = s >> 2;
        int cc  = (s & 3) << 3;               // bf16 col within 32
        uint32_t o = (uint32_t)(row * 40 + cc) * 2u;
        long long ga = (long long)(m0 + row) * lda + k0 + cc;
        long long gb = (long long)(n0 + row) * ldb + k0 + cc;
        cpa(sb + o,          &Ah[ga]);
        cpa(sb + 10240u + o, &Al[ga]);
        cpa(sb + 20480u + o, &Bh[gb]);
        cpa(sb + 30720u + o, &Bl[gb]);
    }
}

__device__ __forceinline__ void compute_tile(uint32_t sb, int wm, int wn, int lane,
                                             float acc[4][4][4])
{
    const int aRow = lane & 15;
    const int aK   = (lane & 16) ? 8 : 0;
    const int bRow = (lane & 7) + ((lane & 16) ? 8 : 0);
    const int bK   = (lane & 8) ? 8 : 0;
    #pragma unroll
    for (int kh = 0; kh < 32; kh += 16) {
        uint32_t ah[4][4];
        uint32_t al[4][4];
        uint32_t bh[2][4];
        uint32_t bl[2][4];
        #pragma unroll
        for (int mt = 0; mt < 4; mt++) {
            uint32_t off = (uint32_t)((wm + mt * 16 + aRow) * 40 + kh + aK) * 2u;
            ldsm4(ah[mt], sb + off);
            ldsm4(al[mt], sb + 10240u + off);
        }
        #pragma unroll
        for (int pr = 0; pr < 2; pr++) {
            uint32_t off = (uint32_t)((wn + pr * 16 + bRow) * 40 + kh + bK) * 2u;
            ldsm4(bh[pr], sb + 20480u + off);
            ldsm4(bl[pr], sb + 30720u + off);
        }
        #pragma unroll
        for (int mt = 0; mt < 4; mt++)
            #pragma unroll
            for (int nt = 0; nt < 4; nt++)
                mma_bf16(acc[mt][nt], ah[mt], &bh[nt >> 1][(nt & 1) * 2]);
        #pragma unroll
        for (int mt = 0; mt < 4; mt++)
            #pragma unroll
            for (int nt = 0; nt < 4; nt++)
                mma_bf16(acc[mt][nt], ah[mt], &bl[nt >> 1][(nt & 1) * 2]);
        #pragma unroll
        for (int mt = 0; mt < 4; mt++)
            #pragma unroll
            for (int nt = 0; nt < 4; nt++)
                mma_bf16(acc[mt][nt], al[mt], &bh[nt >> 1][(nt & 1) * 2]);
    }
}

// ---------------- GEMM: C = alpha*A@B^T (+bias)(+gelu) ----------------
// A hi/lo [M,K] bf16, B hi/lo [N,K] bf16. OUT: 0 fp32 C; 1 split bf16 Ch/Cl.
// Tile 128x128, KT=32, 3-stage cp.async. grid(x=N/128, y=M/128, z=batch).
template<int OUT, int ACT>
__global__ __launch_bounds__(256, 1)
void gemm_bf(const __nv_bfloat16* __restrict__ Ah, const __nv_bfloat16* __restrict__ Al,
             const __nv_bfloat16* __restrict__ Bh, const __nv_bfloat16* __restrict__ Bl,
             float* __restrict__ C,
             __nv_bfloat16* __restrict__ Ch, __nv_bfloat16* __restrict__ Cl,
             const float* __restrict__ bias,
             int K, int lda, int ldb, int ldc,
             long long sA, long long sB, long long sC, float alpha)
{
    extern __shared__ __align__(128) char smem[];
    const int tid = threadIdx.x;
    const int lane = tid & 31;
    const int warp = tid >> 5;
    const int wm = (warp >> 2) * 64;
    const int wn = (warp & 3) * 32;

    Ah += sA * blockIdx.z; Al += sA * blockIdx.z;
    Bh += sB * blockIdx.z; Bl += sB * blockIdx.z;
    if (OUT == 0) { C += sC * blockIdx.z; }
    else          { Ch += sC * blockIdx.z; Cl += sC * blockIdx.z; }

    const int m0 = blockIdx.y * 128;
    const int n0 = blockIdx.x * 128;
    const uint32_t sbase = (uint32_t)__cvta_generic_to_shared(smem);

    float acc[4][4][4];
    #pragma unroll
    for (int i = 0; i < 4; i++)
        #pragma unroll
        for (int j = 0; j < 4; j++) {
            acc[i][j][0] = 0.f; acc[i][j][1] = 0.f;
            acc[i][j][2] = 0.f; acc[i][j][3] = 0.f;
        }

    const int NC = K >> 5;   // KT=32; all K are multiples of 32, NC >= 4

    // prologue: stages 0..1
    #pragma unroll
    for (int p = 0; p < 2; p++) {
        issue_tile(Ah, Al, Bh, Bl, tid, m0, n0, lda, ldb, p * 32,
                   sbase + (uint32_t)p * 40960u);
        asm volatile("cp.async.commit_group;" ::: "memory");
    }

    for (int c = 0; c < NC; c++) {
        const int nc = c + 2;
        if (nc < NC)
            issue_tile(Ah, Al, Bh, Bl, tid, m0, n0, lda, ldb, nc * 32,
                       sbase + (uint32_t)(nc % 3) * 40960u);
        asm volatile("cp.async.commit_group;" ::: "memory");
        asm volatile("cp.async.wait_group 2;" ::: "memory");
        __syncthreads();
        compute_tile(sbase + (uint32_t)(c % 3) * 40960u, wm, wn, lane, acc);
        __syncthreads();
    }

    // epilogue
    const int crow = lane >> 2;
    const int ccol = (lane & 3) << 1;
    #pragma unroll
    for (int mt = 0; mt < 4; mt++) {
        #pragma unroll
        for (int nt = 0; nt < 4; nt++) {
            const int gn = n0 + wn + nt * 8 + ccol;
            #pragma unroll
            for (int half = 0; half < 2; half++) {
                const int gm = m0 + wm + mt * 16 + crow + half * 8;
                float v0 = acc[mt][nt][half * 2 + 0] * alpha;
                float v1 = acc[mt][nt][half * 2 + 1] * alpha;
                if (bias) { v0 += bias[gn]; v1 += bias[gn + 1]; }
                if (ACT == 1) {
                    float x = v0;
                    v0 = 0.5f * x * (1.f + tanhf(0.7978845608028654f *
                                                 (x + 0.044715f * x * x * x)));
                    x = v1;
                    v1 = 0.5f * x * (1.f + tanhf(0.7978845608028654f *
                                                 (x + 0.044715f * x * x * x)));
                }
                const long long ci = (long long)gm * ldc + gn;
                if (OUT == 0) {
                    *reinterpret_cast<float2*>(&C[ci]) = make_float2(v0, v1);
                } else {
                    __nv_bfloat16 h0, l0, h1, l1;
                    split1(v0, h0, l0);
                    split1(v1, h1, l1);
                    *reinterpret_cast<__nv_bfloat162*>(&Ch[ci]) = __nv_bfloat162(h0, h1);
                    *reinterpret_cast<__nv_bfloat162*>(&Cl[ci]) = __nv_bfloat162(l0, l1);
                }
            }
        }
    }
}

// ---------------- weight split (fp32 -> bf16 hi/lo planes) ----------------
__global__ __launch_bounds__(256)
void wsplit_kernel(const float* __restrict__ s, __nv_bfloat16* __restrict__ h,
                   __nv_bfloat16* __restrict__ l, int n4)
{
    int i = blockIdx.x * blockDim.x + threadIdx.x;
    const int stride = gridDim.x * blockDim.x;
    for (; i < n4; i += stride) {
        float4 v = reinterpret_cast<const float4*>(s)[i];
        __nv_bfloat16 h0, l0, h1, l1, h2, l2, h3, l3;
        split1(v.x, h0, l0); split1(v.y, h1, l1);
        split1(v.z, h2, l2); split1(v.w, h3, l3);
        reinterpret_cast<__nv_bfloat162*>(h)[i * 2]     = __nv_bfloat162(h0, h1);
        reinterpret_cast<__nv_bfloat162*>(h)[i * 2 + 1] = __nv_bfloat162(h2, h3);
        reinterpret_cast<__nv_bfloat162*>(l)[i * 2]     = __nv_bfloat162(l0, l1);
        reinterpret_cast<__nv_bfloat162*>(l)[i * 2 + 1] = __nv_bfloat162(l2, l3);
    }
}

// ---------------- LN + adaLN modulation -> split planes ----------------
__global__ __launch_bounds__(256)
void lnmod_attn_kernel(const float* __restrict__ img_e, const float* __restrict__ txt_e,
                       const float* __restrict__ i_sc, const float* __restrict__ i_sh,
                       const float* __restrict__ t_sc, const float* __restrict__ t_sh,
                       __nv_bfloat16* __restrict__ oh, __nv_bfloat16* __restrict__ ol)
{
    const int row = blockIdx.x;
    const bool is_txt = row < LTXT;
    const float* x  = is_txt ? txt_e + (size_t)row * DIM : img_e + (size_t)(row - LTXT) * DIM;
    const float* sc = is_txt ? t_sc : i_sc;
    const float* sh = is_txt ? t_sh : i_sh;
    __shared__ float red[8];
    const int tid = threadIdx.x;
    float v[12];
    float s = 0.f, ss = 0.f;
    #pragma unroll
    for (int i = 0; i < 12; i++) {
        float a = x[tid + i * 256];
        v[i] = a; s += a; ss += a * a;
    }
    s  = blk_sum<8>(s,  red);
    ss = blk_sum<8>(ss, red);
    const float m   = s * (1.f / DIM);
    const float var = ss * (1.f / DIM) - m * m;
    const float rs  = rsqrtf(var + 1e-6f);
    #pragma unroll
    for (int i = 0; i < 12; i++) {
        const int c = tid + i * 256;
        float y = (1.f + sc[c]) * (v[i] - m) * rs + sh[c];
        __nv_bfloat16 h, l;
        split1(y, h, l);
        oh[(size_t)row * DIM + c] = h;
        ol[(size_t)row * DIM + c] = l;
    }
}

// ---------------- qkv split + RMSNorm(q,k) + RoPE -> split planes ----------
__global__ __launch_bounds__(128)
void qkv_post_kernel(const float* __restrict__ qkv, const float* __restrict__ pe,
                     const float* __restrict__ img_w, const float* __restrict__ txt_w,
                     __nv_bfloat16* __restrict__ qh, __nv_bfloat16* __restrict__ ql,
                     __nv_bfloat16* __restrict__ kh, __nv_bfloat16* __restrict__ kl,
                     __nv_bfloat16* __restrict__ vth, __nv_bfloat16* __restrict__ vtl)
{
    const int row = blockIdx.x;
    const int h   = blockIdx.y;
    const int d   = threadIdx.x;
    const float* w = (row < LTXT) ? txt_w : img_w;

    const size_t base = (size_t)row * (3 * DIM) + (size_t)h * DH + d;
    const float qv = qkv[base];
    const float kv = qkv[base + DIM];
    const float vv = qkv[base + 2 * DIM];

    __shared__ float shq[4], shk[4], bc[2];
    __shared__ float qn[DH], kn[DH];

    float qs = qv * qv, ks = kv * kv;
    #pragma unroll
    for (int o = 16; o; o >>= 1) {
        qs += __shfl_down_sync(0xffffffffu, qs, o);
        ks += __shfl_down_sync(0xffffffffu, ks, o);
    }
    const int lane = d & 31, wp = d >> 5;
    if (lane == 0) { shq[wp] = qs; shk[wp] = ks; }
    __syncthreads();
    if (d == 0) bc[0] = rsqrtf((shq[0] + shq[1] + shq[2] + shq[3]) * (1.f / DH) + 1e-6f);
    if (d == 1) bc[1] = rsqrtf((shk[0] + shk[1] + shk[2] + shk[3]) * (1.f / DH) + 1e-6f);
    __syncthreads();

    qn[d] = qv * bc[0] * w[d];
    kn[d] = kv * bc[1] * w[d];
    __syncthreads();

    const int d2 = d >> 1;
    const float c = pe[(size_t)row * 256 + d2 * 4 + 0];
    const float s = pe[(size_t)row * 256 + d2 * 4 + 2];
    const float qr = qn[d2 * 2], qi = qn[d2 * 2 + 1];
    const float kr = kn[d2 * 2], ki = kn[d2 * 2 + 1];
    const float qo = (d & 1) ? (qr * s + qi * c) : (qr * c - qi * s);
    const float ko = (d & 1) ? (kr * s + ki * c) : (kr * c - ki * s);

    const size_t o = ((size_t)h * LL + row) * DH + d;
    __nv_bfloat16 hh, ll;
    split1(qo, hh, ll); qh[o] = hh; ql[o] = ll;
    split1(ko, hh, ll); kh[o] = hh; kl[o] = ll;
    const size_t ov = ((size_t)h * DH + d) * LL + row;
    split1(vv, hh, ll); vth[ov] = hh; vtl[ov] = ll;
}

// ---------------- row softmax -> split planes ----------------
__global__ __launch_bounds__(256)
void softmax_kernel(const float* __restrict__ sc,
                    __nv_bfloat16* __restrict__ ph, __nv_bfloat16* __restrict__ pl)
{
    const float* p = sc + (size_t)blockIdx.x * LL;
    __nv_bfloat16* oh = ph + (size_t)blockIdx.x * LL;
    __nv_bfloat16* ol = pl + (size_t)blockIdx.x * LL;
    const int tid = threadIdx.x;
    __shared__ float red[8];
    float v[8];
    float mx = -1e30f;
    #pragma unroll
    for (int i = 0; i < 8; i++) { v[i] = p[tid + i * 256]; mx = fmaxf(mx, v[i]); }
    mx = blk_max<8>(mx, red);
    float sum = 0.f;
    #pragma unroll
    for (int i = 0; i < 8; i++) { v[i] = expf(v[i] - mx); sum += v[i]; }
    sum = blk_sum<8>(sum, red);
    const float inv = 1.f / sum;
    #pragma unroll
    for (int i = 0; i < 8; i++) {
        __nv_bfloat16 h, l;
        split1(v[i] * inv, h, l);
        oh[tid + i * 256] = h;
        ol[tid + i * 256] = l;
    }
}

// ---------------- attn residual (gated) + LN + MLP modulation ----------------
__global__ __launch_bounds__(256)
void resid_lnmod_kernel(const float* __restrict__ proj,
                        const float* __restrict__ img_e, const float* __restrict__ txt_e,
                        const float* __restrict__ i_gate, const float* __restrict__ t_gate,
                        const float* __restrict__ i_sc, const float* __restrict__ i_sh,
                        const float* __restrict__ t_sc, const float* __restrict__ t_sh,
                        float* __restrict__ resid,
                        __nv_bfloat16* __restrict__ mih, __nv_bfloat16* __restrict__ mil)
{
    const int row = blockIdx.x;
    const bool is_txt = row < LTXT;
    const float* e  = is_txt ? txt_e + (size_t)row * DIM : img_e + (size_t)(row - LTXT) * DIM;
    const float* g  = is_txt ? t_gate : i_gate;
    const float* sc = is_txt ? t_sc : i_sc;
    const float* sh = is_txt ? t_sh : i_sh;
    __shared__ float red[8];
    const int tid = threadIdx.x;
    float r[12];
    float s = 0.f, ss = 0.f;
    #pragma unroll
    for (int i = 0; i < 12; i++) {
        const int c = tid + i * 256;
        float x = e[c] + g[c] * proj[(size_t)row * DIM + c];
        r[i] = x; s += x; ss += x * x;
        resid[(size_t)row * DIM + c] = x;
    }
    s  = blk_sum<8>(s,  red);
    ss = blk_sum<8>(ss, red);
    const float m   = s * (1.f / DIM);
    const float var = ss * (1.f / DIM) - m * m;
    const float rs  = rsqrtf(var + 1e-6f);
    #pragma unroll
    for (int i = 0; i < 12; i++) {
        const int c = tid + i * 256;
        float y = (1.f + sc[c]) * (r[i] - m) * rs + sh[c];
        __nv_bfloat16 h, l;
        split1(y, h, l);
        mih[(size_t)row * DIM + c] = h;
        mil[(size_t)row * DIM + c] = l;
    }
}

// ---------------- final gated residual -> d_out ----------------
__global__ __launch_bounds__(256)
void final_kernel(const float* __restrict__ mlpout, const float* __restrict__ resid,
                  const float* __restrict__ i_gate, const float* __restrict__ t_gate,
                  float* __restrict__ out)
{
    const int row = blockIdx.x;
    const int tid = threadIdx.x;
    const bool is_txt = row < LTXT;
    const float* g = is_txt ? t_gate : i_gate;
    float* dst = is_txt ? out + (size_t)LIMG * DIM + (size_t)row * DIM
                        : out + (size_t)(row - LTXT) * DIM;
    #pragma unroll
    for (int i = 0; i < 12; i++) {
        const int c = tid + i * 256;
        dst[c] = resid[(size_t)row * DIM + c] + g[c] * mlpout[(size_t)row * DIM + c];
    }
}

// ---------------- launch ----------------
extern "C" void kernel_launch(void* const* d_in, const int* in_sizes, int n_in,
                              void* d_out, int out_size)
{
    const float* img_e       = (const float*)d_in[0];
    const float* txt_e       = (const float*)d_in[1];
    const float* pe          = (const float*)d_in[2];
    const float* i_attn_sc   = (const float*)d_in[3];
    const float* i_attn_sh   = (const float*)d_in[4];
    const float* i_attn_gate = (const float*)d_in[5];
    const float* i_mlp_sc    = (const float*)d_in[6];
    const float* i_mlp_sh    = (const float*)d_in[7];
    const float* i_mlp_gate  = (const float*)d_in[8];
    const float* t_attn_sc   = (const float*)d_in[9];
    const float* t_attn_sh   = (const float*)d_in[10];
    const float* t_attn_gate = (const float*)d_in[11];
    const float* t_mlp_sc    = (const float*)d_in[12];
    const float* t_mlp_sh    = (const float*)d_in[13];
    const float* t_mlp_gate  = (const float*)d_in[14];
    const float* i_qkv_w     = (const float*)d_in[15];
    const float* i_qkv_b     = (const float*)d_in[16];
    const float* i_qknorm    = (const float*)d_in[17];
    const float* t_qkv_w     = (const float*)d_in[18];
    const float* t_qkv_b     = (const float*)d_in[19];
    const float* t_qknorm    = (const float*)d_in[20];
    const float* proj_w      = (const float*)d_in[21];
    const float* proj_b      = (const float*)d_in[22];
    const float* i_mlp_w1    = (const float*)d_in[23];
    const float* i_mlp_b1    = (const float*)d_in[24];
    const float* i_mlp_w2    = (const float*)d_in[25];
    const float* i_mlp_b2    = (const float*)d_in[26];
    const float* t_mlp_w1    = (const float*)d_in[27];
    const float* t_mlp_b1    = (const float*)d_in[28];
    const float* t_mlp_w2    = (const float*)d_in[29];
    const float* t_mlp_b2    = (const float*)d_in[30];
    // d_in[31] = mask (all-true; unused)

    __nv_bfloat16 *wh, *wl, *xmh, *xml, *qh, *ql, *kh, *kl, *vth, *vtl;
    __nv_bfloat16 *ph, *pl, *ath, *atl, *mih, *mil, *mhh, *mhl;
    float *qkv, *scores, *proj, *resid, *mlpout;
    cudaGetSymbolAddress((void**)&wh,    g_wh);
    cudaGetSymbolAddress((void**)&wl,    g_wl);
    cudaGetSymbolAddress((void**)&xmh,   g_xmh);
    cudaGetSymbolAddress((void**)&xml,   g_xml);
    cudaGetSymbolAddress((void**)&qkv,   g_qkv);
    cudaGetSymbolAddress((void**)&qh,    g_qh);
    cudaGetSymbolAddress((void**)&ql,    g_ql);
    cudaGetSymbolAddress((void**)&kh,    g_kh);
    cudaGetSymbolAddress((void**)&kl,    g_kl);
    cudaGetSymbolAddress((void**)&vth,   g_vth);
    cudaGetSymbolAddress((void**)&vtl,   g_vtl);
    cudaGetSymbolAddress((void**)&scores, g_scores);
    cudaGetSymbolAddress((void**)&ph,    g_ph);
    cudaGetSymbolAddress((void**)&pl,    g_pl);
    cudaGetSymbolAddress((void**)&ath,   g_ath);
    cudaGetSymbolAddress((void**)&atl,   g_atl);
    cudaGetSymbolAddress((void**)&proj,  g_proj);
    cudaGetSymbolAddress((void**)&resid, g_resid);
    cudaGetSymbolAddress((void**)&mih,   g_mih);
    cudaGetSymbolAddress((void**)&mil,   g_mil);
    cudaGetSymbolAddress((void**)&mhh,   g_mhh);
    cudaGetSymbolAddress((void**)&mhl,   g_mhl);
    cudaGetSymbolAddress((void**)&mlpout, g_mlpout);

    const float attn_scale = 0.08838834764831845f;  // 1/sqrt(128)
    const int SMEM = 3 * 40960;                     // 122880 B

    cudaFuncSetAttribute(gemm_bf<0, 0>, cudaFuncAttributeMaxDynamicSharedMemorySize, SMEM);
    cudaFuncSetAttribute(gemm_bf<1, 0>, cudaFuncAttributeMaxDynamicSharedMemorySize, SMEM);
    cudaFuncSetAttribute(gemm_bf<1, 1>, cudaFuncAttributeMaxDynamicSharedMemorySize, SMEM);

    // 0) weight splits
    wsplit_kernel<<<1024, 256>>>(t_qkv_w,  wh + W_TQKV, wl + W_TQKV, 3 * DIM * DIM / 4);
    wsplit_kernel<<<1024, 256>>>(i_qkv_w,  wh + W_IQKV, wl + W_IQKV, 3 * DIM * DIM / 4);
    wsplit_kernel<<<1024, 256>>>(proj_w,   wh + W_PROJ, wl + W_PROJ, DIM * DIM / 4);
    wsplit_kernel<<<1024, 256>>>(t_mlp_w1, wh + W_TW1,  wl + W_TW1,  MLPD * DIM / 4);
    wsplit_kernel<<<1024, 256>>>(i_mlp_w1, wh + W_IW1,  wl + W_IW1,  MLPD * DIM / 4);
    wsplit_kernel<<<1024, 256>>>(t_mlp_w2, wh + W_TW2,  wl + W_TW2,  DIM * MLPD / 4);
    wsplit_kernel<<<1024, 256>>>(i_mlp_w2, wh + W_IW2,  wl + W_IW2,  DIM * MLPD / 4);

    // 1) LN + attention modulation -> split planes
    lnmod_attn_kernel<<<LL, 256>>>(img_e, txt_e, i_attn_sc, i_attn_sh,
                                   t_attn_sc, t_attn_sh, xmh, xml);

    // 2) QKV GEMMs -> fp32 qkv
    gemm_bf<0, 0><<<dim3(3 * DIM / 128, LTXT / 128, 1), 256, SMEM>>>(
        xmh, xml, wh + W_TQKV, wl + W_TQKV, qkv, nullptr, nullptr, t_qkv_b,
        DIM, DIM, DIM, 3 * DIM, 0, 0, 0, 1.f);
    gemm_bf<0, 0><<<dim3(3 * DIM / 128, LIMG / 128, 1), 256, SMEM>>>(
        xmh + (size_t)LTXT * DIM, xml + (size_t)LTXT * DIM,
        wh + W_IQKV, wl + W_IQKV, qkv + (size_t)LTXT * 3 * DIM, nullptr, nullptr, i_qkv_b,
        DIM, DIM, DIM, 3 * DIM, 0, 0, 0, 1.f);

    // 3) split + RMSNorm + RoPE -> q/k planes, v transposed planes
    qkv_post_kernel<<<dim3(LL, NH), 128>>>(qkv, pe, i_qknorm, t_qknorm,
                                           qh, ql, kh, kl, vth, vtl);

    // 4) scores = scale * q @ k^T -> fp32
    gemm_bf<0, 0><<<dim3(LL / 128, LL / 128, NH), 256, SMEM>>>(
        qh, ql, kh, kl, scores, nullptr, nullptr, nullptr,
        DH, DH, DH, LL,
        (long long)LL * DH, (long long)LL * DH, (long long)LL * LL, attn_scale);

    // 5) softmax -> p planes
    softmax_kernel<<<NH * LL, 256>>>(scores, ph, pl);

    // 6) o = p @ v^T -> attn planes (OUT=1)
    gemm_bf<1, 0><<<dim3(1, LL / 128, NH), 256, SMEM>>>(
        ph, pl, vth, vtl, nullptr, ath, atl, nullptr,
        LL, LL, LL, DIM,
        (long long)LL * LL, (long long)DH * LL, (long long)DH, 1.f);

    // 7) shared projection -> fp32
    gemm_bf<0, 0><<<dim3(DIM / 128, LL / 128, 1), 256, SMEM>>>(
        ath, atl, wh + W_PROJ, wl + W_PROJ, proj, nullptr, nullptr, proj_b,
        DIM, DIM, DIM, DIM, 0, 0, 0, 1.f);

    // 8) gated attn residual + LN + MLP modulation -> resid fp32, mlpin planes
    resid_lnmod_kernel<<<LL, 256>>>(proj, img_e, txt_e,
                                    i_attn_gate, t_attn_gate,
                                    i_mlp_sc, i_mlp_sh, t_mlp_sc, t_mlp_sh,
                                    resid, mih, mil);

    // 9) MLP up (bias+gelu fused) -> mlph planes
    gemm_bf<1, 1><<<dim3(MLPD / 128, LTXT / 128, 1), 256, SMEM>>>(
        mih, mil, wh + W_TW1, wl + W_TW1, nullptr, mhh, mhl, t_mlp_b1,
        DIM, DIM, DIM, MLPD, 0, 0, 0, 1.f);
    gemm_bf<1, 1><<<dim3(MLPD / 128, LIMG / 128, 1), 256, SMEM>>>(
        mih + (size_t)LTXT * DIM, mil + (size_t)LTXT * DIM,
        wh + W_IW1, wl + W_IW1, nullptr,
        mhh + (size_t)LTXT * MLPD, mhl + (size_t)LTXT * MLPD, i_mlp_b1,
        DIM, DIM, DIM, MLPD, 0, 0, 0, 1.f);

    // 10) MLP down -> fp32
    gemm_bf<0, 0><<<dim3(DIM / 128, LTXT / 128, 1), 256, SMEM>>>(
        mhh, mhl, wh + W_TW2, wl + W_TW2, mlpout, nullptr, nullptr, t_mlp_b2,
        MLPD, MLPD, MLPD, DIM, 0, 0, 0, 1.f);
    gemm_bf<0, 0><<<dim3(DIM / 128, LIMG / 128, 1), 256, SMEM>>>(
        mhh + (size_t)LTXT * MLPD, mhl + (size_t)LTXT * MLPD,
        wh + W_IW2, wl + W_IW2, mlpout + (size_t)LTXT * DIM, nullptr, nullptr, i_mlp_b2,
        MLPD, MLPD, MLPD, DIM, 0, 0, 0, 1.f);

    // 11) final gated residual -> output (img block first, then txt block)
    final_kernel<<<LL, 256>>>(mlpout, resid, i_mlp_gate, t_mlp_gate, (float*)d_out);
}

// round 7
// speedup vs baseline: 6.5215x; 2.4908x over previous
#include <cuda_runtime.h>
#include <cuda_bf16.h>
#include <stdint.h>
#include <math.h>

// ---------------- problem constants ----------------
#define LL    2048
#define LTXT  512
#define LIMG  1536
#define DIM   3072
#define NH    24
#define DH    128
#define MLPD  12288

// weight plane offsets (elements)
#define W_TQKV 0LL
#define W_IQKV (W_TQKV + (long long)3*DIM*DIM)
#define W_PROJ (W_IQKV + (long long)3*DIM*DIM)
#define W_TW1  (W_PROJ + (long long)DIM*DIM)
#define W_IW1  (W_TW1  + (long long)MLPD*DIM)
#define W_TW2  (W_IW1  + (long long)MLPD*DIM)
#define W_IW2  (W_TW2  + (long long)DIM*MLPD)
#define W_TOT  (W_IW2  + (long long)DIM*MLPD)

// ---------------- scratch (bf16 hi-planes only) ----------------
__device__ __nv_bfloat16 g_wh [W_TOT];
__device__ __nv_bfloat16 g_xmh[(size_t)LL * DIM];
__device__ float         g_qkv[(size_t)LL * 3 * DIM];
__device__ __nv_bfloat16 g_qh [(size_t)NH * LL * DH];
__device__ __nv_bfloat16 g_kh [(size_t)NH * LL * DH];
__device__ __nv_bfloat16 g_vth[(size_t)NH * DH * LL];   // [h][dh][l]
__device__ float         g_scores[(size_t)NH * LL * LL];
__device__ __nv_bfloat16 g_ph [(size_t)NH * LL * LL];
__device__ __nv_bfloat16 g_ath[(size_t)LL * DIM];
__device__ float         g_proj[(size_t)LL * DIM];
__device__ float         g_resid[(size_t)LL * DIM];
__device__ __nv_bfloat16 g_mih[(size_t)LL * DIM];
__device__ __nv_bfloat16 g_mhh[(size_t)LL * MLPD];
__device__ float         g_mlpout[(size_t)LL * DIM];

// ---------------- reductions ----------------
template<int NW>
__device__ __forceinline__ float blk_sum(float v, float* sh) {
    #pragma unroll
    for (int o = 16; o; o >>= 1) v += __shfl_down_sync(0xffffffffu, v, o);
    int lane = threadIdx.x & 31, w = threadIdx.x >> 5;
    if (lane == 0) sh[w] = v;
    __syncthreads();
    if (threadIdx.x == 0) {
        float r = 0.f;
        #pragma unroll
        for (int i = 0; i < NW; i++) r += sh[i];
        sh[0] = r;
    }
    __syncthreads();
    float r = sh[0];
    __syncthreads();
    return r;
}

template<int NW>
__device__ __forceinline__ float blk_max(float v, float* sh) {
    #pragma unroll
    for (int o = 16; o; o >>= 1) v = fmaxf(v, __shfl_down_sync(0xffffffffu, v, o));
    int lane = threadIdx.x & 31, w = threadIdx.x >> 5;
    if (lane == 0) sh[w] = v;
    __syncthreads();
    if (threadIdx.x == 0) {
        float r = sh[0];
        #pragma unroll
        for (int i = 1; i < NW; i++) r = fmaxf(r, sh[i]);
        sh[0] = r;
    }
    __syncthreads();
    float r = sh[0];
    __syncthreads();
    return r;
}

// ---------------- tensor-core primitives ----------------
__device__ __forceinline__ void mma_bf16(float d[4], const uint32_t a[4],
                                         const uint32_t b[2]) {
    asm volatile(
        "mma.sync.aligned.m16n8k16.row.col.f32.bf16.bf16.f32 "
        "{%0,%1,%2,%3},{%4,%5,%6,%7},{%8,%9},{%0,%1,%2,%3};"
        : "+f"(d[0]), "+f"(d[1]), "+f"(d[2]), "+f"(d[3])
        : "r"(a[0]), "r"(a[1]), "r"(a[2]), "r"(a[3]), "r"(b[0]), "r"(b[1]));
}

__device__ __forceinline__ void ldsm4(uint32_t r[4], uint32_t addr) {
    asm volatile("ldmatrix.sync.aligned.m8n8.x4.shared.b16 {%0,%1,%2,%3}, [%4];"
                 : "=r"(r[0]), "=r"(r[1]), "=r"(r[2]), "=r"(r[3]) : "r"(addr));
}

__device__ __forceinline__ void cpa(uint32_t d, const void* s) {
    asm volatile("cp.async.cg.shared.global [%0], [%1], 16;" :: "r"(d), "l"(s));
}

// ---------------- GEMM staging / compute ----------------
// smem stage layout: Ah[128][40], Bh[128][40] — 10240 B each, 20480 B per stage.
__device__ __forceinline__ void issue_tile(
    const __nv_bfloat16* __restrict__ Ah, const __nv_bfloat16* __restrict__ Bh,
    int tid, int m0, int n0, int lda, int ldb, int k0, uint32_t sb)
{
    #pragma unroll
    for (int i = 0; i < 2; i++) {
        int s = tid + i * 256;
        int row = s >> 2;
        int cc  = (s & 3) << 3;               // bf16 col within 32
        uint32_t o = (uint32_t)(row * 40 + cc) * 2u;
        cpa(sb + o,          &Ah[(long long)(m0 + row) * lda + k0 + cc]);
        cpa(sb + 10240u + o, &Bh[(long long)(n0 + row) * ldb + k0 + cc]);
    }
}

__device__ __forceinline__ void compute_tile(uint32_t sb, int wm, int wn, int lane,
                                             float acc[4][4][4])
{
    const int aRow = lane & 15;
    const int aK   = (lane & 16) ? 8 : 0;
    const int bRow = (lane & 7) + ((lane & 16) ? 8 : 0);
    const int bK   = (lane & 8) ? 8 : 0;
    #pragma unroll
    for (int kh = 0; kh < 32; kh += 16) {
        uint32_t ah[4][4];
        uint32_t bh[2][4];
        #pragma unroll
        for (int mt = 0; mt < 4; mt++) {
            uint32_t off = (uint32_t)((wm + mt * 16 + aRow) * 40 + kh + aK) * 2u;
            ldsm4(ah[mt], sb + off);
        }
        #pragma unroll
        for (int pr = 0; pr < 2; pr++) {
            uint32_t off = (uint32_t)((wn + pr * 16 + bRow) * 40 + kh + bK) * 2u;
            ldsm4(bh[pr], sb + 10240u + off);
        }
        #pragma unroll
        for (int mt = 0; mt < 4; mt++)
            #pragma unroll
            for (int nt = 0; nt < 4; nt++)
                mma_bf16(acc[mt][nt], ah[mt], &bh[nt >> 1][(nt & 1) * 2]);
    }
}

// ---------------- GEMM: C = alpha*A@B^T (+bias)(+gelu) ----------------
// A [M,K] bf16, B [N,K] bf16. OUT: 0 fp32 C; 1 bf16 Ch.
// Optional second weight set: blocks with m0 >= mswitch use Bh2/bias2.
// Tile 128x128, KT=32, 3-stage cp.async. grid(x=N/128, y=M/128, z=batch).
template<int OUT, int ACT>
__global__ __launch_bounds__(256, 2)
void gemm_bf(const __nv_bfloat16* __restrict__ Ah,
             const __nv_bfloat16* __restrict__ Bh,
             const __nv_bfloat16* __restrict__ Bh2,
             float* __restrict__ C, __nv_bfloat16* __restrict__ Ch,
             const float* __restrict__ bias, const float* __restrict__ bias2,
             int mswitch, int K, int lda, int ldb, int ldc,
             long long sA, long long sB, long long sC, float alpha)
{
    extern __shared__ __align__(128) char smem[];
    const int tid = threadIdx.x;
    const int lane = tid & 31;
    const int warp = tid >> 5;
    const int wm = (warp >> 2) * 64;
    const int wn = (warp & 3) * 32;

    const int m0 = blockIdx.y * 128;
    const int n0 = blockIdx.x * 128;

    Ah += sA * blockIdx.z;
    Bh += sB * blockIdx.z;
    if (Bh2 && m0 >= mswitch) { Bh = Bh2; bias = bias2; }
    if (OUT == 0) C  += sC * blockIdx.z;
    else          Ch += sC * blockIdx.z;

    const uint32_t sbase = (uint32_t)__cvta_generic_to_shared(smem);

    float acc[4][4][4];
    #pragma unroll
    for (int i = 0; i < 4; i++)
        #pragma unroll
        for (int j = 0; j < 4; j++) {
            acc[i][j][0] = 0.f; acc[i][j][1] = 0.f;
            acc[i][j][2] = 0.f; acc[i][j][3] = 0.f;
        }

    const int NC = K >> 5;   // KT=32

    #pragma unroll
    for (int p = 0; p < 2; p++) {
        issue_tile(Ah, Bh, tid, m0, n0, lda, ldb, p * 32,
                   sbase + (uint32_t)p * 20480u);
        asm volatile("cp.async.commit_group;" ::: "memory");
    }

    for (int c = 0; c < NC; c++) {
        const int nc = c + 2;
        if (nc < NC)
            issue_tile(Ah, Bh, tid, m0, n0, lda, ldb, nc * 32,
                       sbase + (uint32_t)(nc % 3) * 20480u);
        asm volatile("cp.async.commit_group;" ::: "memory");
        asm volatile("cp.async.wait_group 2;" ::: "memory");
        __syncthreads();
        compute_tile(sbase + (uint32_t)(c % 3) * 20480u, wm, wn, lane, acc);
        __syncthreads();
    }

    // epilogue
    const int crow = lane >> 2;
    const int ccol = (lane & 3) << 1;
    #pragma unroll
    for (int mt = 0; mt < 4; mt++) {
        #pragma unroll
        for (int nt = 0; nt < 4; nt++) {
            const int gn = n0 + wn + nt * 8 + ccol;
            #pragma unroll
            for (int half = 0; half < 2; half++) {
                const int gm = m0 + wm + mt * 16 + crow + half * 8;
                float v0 = acc[mt][nt][half * 2 + 0] * alpha;
                float v1 = acc[mt][nt][half * 2 + 1] * alpha;
                if (bias) { v0 += bias[gn]; v1 += bias[gn + 1]; }
                if (ACT == 1) {
                    float x = v0;
                    v0 = 0.5f * x * (1.f + tanhf(0.7978845608028654f *
                                                 (x + 0.044715f * x * x * x)));
                    x = v1;
                    v1 = 0.5f * x * (1.f + tanhf(0.7978845608028654f *
                                                 (x + 0.044715f * x * x * x)));
                }
                const long long ci = (long long)gm * ldc + gn;
                if (OUT == 0) {
                    *reinterpret_cast<float2*>(&C[ci]) = make_float2(v0, v1);
                } else {
                    *reinterpret_cast<__nv_bfloat162*>(&Ch[ci]) =
                        __nv_bfloat162(__float2bfloat16(v0), __float2bfloat16(v1));
                }
            }
        }
    }
}

// ---------------- weight convert (fp32 -> bf16) ----------------
__global__ __launch_bounds__(256)
void wcvt_kernel(const float* __restrict__ s, __nv_bfloat16* __restrict__ h, int n4)
{
    int i = blockIdx.x * blockDim.x + threadIdx.x;
    const int stride = gridDim.x * blockDim.x;
    for (; i < n4; i += stride) {
        float4 v = reinterpret_cast<const float4*>(s)[i];
        reinterpret_cast<__nv_bfloat162*>(h)[i * 2] =
            __nv_bfloat162(__float2bfloat16(v.x), __float2bfloat16(v.y));
        reinterpret_cast<__nv_bfloat162*>(h)[i * 2 + 1] =
            __nv_bfloat162(__float2bfloat16(v.z), __float2bfloat16(v.w));
    }
}

// ---------------- LN + adaLN modulation -> bf16 ----------------
__global__ __launch_bounds__(256)
void lnmod_attn_kernel(const float* __restrict__ img_e, const float* __restrict__ txt_e,
                       const float* __restrict__ i_sc, const float* __restrict__ i_sh,
                       const float* __restrict__ t_sc, const float* __restrict__ t_sh,
                       __nv_bfloat16* __restrict__ oh)
{
    const int row = blockIdx.x;
    const bool is_txt = row < LTXT;
    const float* x  = is_txt ? txt_e + (size_t)row * DIM : img_e + (size_t)(row - LTXT) * DIM;
    const float* sc = is_txt ? t_sc : i_sc;
    const float* sh = is_txt ? t_sh : i_sh;
    __shared__ float red[8];
    const int tid = threadIdx.x;
    float v[12];
    float s = 0.f, ss = 0.f;
    #pragma unroll
    for (int i = 0; i < 12; i++) {
        float a = x[tid + i * 256];
        v[i] = a; s += a; ss += a * a;
    }
    s  = blk_sum<8>(s,  red);
    ss = blk_sum<8>(ss, red);
    const float m   = s * (1.f / DIM);
    const float var = ss * (1.f / DIM) - m * m;
    const float rs  = rsqrtf(var + 1e-6f);
    #pragma unroll
    for (int i = 0; i < 12; i++) {
        const int c = tid + i * 256;
        float y = (1.f + sc[c]) * (v[i] - m) * rs + sh[c];
        oh[(size_t)row * DIM + c] = __float2bfloat16(y);
    }
}

// ---------------- qkv split + RMSNorm(q,k) + RoPE -> bf16 ----------
__global__ __launch_bounds__(128)
void qkv_post_kernel(const float* __restrict__ qkv, const float* __restrict__ pe,
                     const float* __restrict__ img_w, const float* __restrict__ txt_w,
                     __nv_bfloat16* __restrict__ qh, __nv_bfloat16* __restrict__ kh,
                     __nv_bfloat16* __restrict__ vth)
{
    const int row = blockIdx.x;
    const int h   = blockIdx.y;
    const int d   = threadIdx.x;
    const float* w = (row < LTXT) ? txt_w : img_w;

    const size_t base = (size_t)row * (3 * DIM) + (size_t)h * DH + d;
    const float qv = qkv[base];
    const float kv = qkv[base + DIM];
    const float vv = qkv[base + 2 * DIM];

    __shared__ float shq[4], shk[4], bc[2];
    __shared__ float qn[DH], kn[DH];

    float qs = qv * qv, ks = kv * kv;
    #pragma unroll
    for (int o = 16; o; o >>= 1) {
        qs += __shfl_down_sync(0xffffffffu, qs, o);
        ks += __shfl_down_sync(0xffffffffu, ks, o);
    }
    const int lane = d & 31, wp = d >> 5;
    if (lane == 0) { shq[wp] = qs; shk[wp] = ks; }
    __syncthreads();
    if (d == 0) bc[0] = rsqrtf((shq[0] + shq[1] + shq[2] + shq[3]) * (1.f / DH) + 1e-6f);
    if (d == 1) bc[1] = rsqrtf((shk[0] + shk[1] + shk[2] + shk[3]) * (1.f / DH) + 1e-6f);
    __syncthreads();

    qn[d] = qv * bc[0] * w[d];
    kn[d] = kv * bc[1] * w[d];
    __syncthreads();

    const int d2 = d >> 1;
    const float c = pe[(size_t)row * 256 + d2 * 4 + 0];
    const float s = pe[(size_t)row * 256 + d2 * 4 + 2];
    const float qr = qn[d2 * 2], qi = qn[d2 * 2 + 1];
    const float kr = kn[d2 * 2], ki = kn[d2 * 2 + 1];
    const float qo = (d & 1) ? (qr * s + qi * c) : (qr * c - qi * s);
    const float ko = (d & 1) ? (kr * s + ki * c) : (kr * c - ki * s);

    const size_t o = ((size_t)h * LL + row) * DH + d;
    qh[o] = __float2bfloat16(qo);
    kh[o] = __float2bfloat16(ko);
    vth[((size_t)h * DH + d) * LL + row] = __float2bfloat16(vv);
}

// ---------------- row softmax -> bf16 ----------------
__global__ __launch_bounds__(256)
void softmax_kernel(const float* __restrict__ sc, __nv_bfloat16* __restrict__ ph)
{
    const float* p = sc + (size_t)blockIdx.x * LL;
    __nv_bfloat16* oh = ph + (size_t)blockIdx.x * LL;
    const int tid = threadIdx.x;
    __shared__ float red[8];
    float v[8];
    float mx = -1e30f;
    #pragma unroll
    for (int i = 0; i < 8; i++) { v[i] = p[tid + i * 256]; mx = fmaxf(mx, v[i]); }
    mx = blk_max<8>(mx, red);
    float sum = 0.f;
    #pragma unroll
    for (int i = 0; i < 8; i++) { v[i] = expf(v[i] - mx); sum += v[i]; }
    sum = blk_sum<8>(sum, red);
    const float inv = 1.f / sum;
    #pragma unroll
    for (int i = 0; i < 8; i++)
        oh[tid + i * 256] = __float2bfloat16(v[i] * inv);
}

// ---------------- attn residual (gated) + LN + MLP modulation ----------------
__global__ __launch_bounds__(256)
void resid_lnmod_kernel(const float* __restrict__ proj,
                        const float* __restrict__ img_e, const float* __restrict__ txt_e,
                        const float* __restrict__ i_gate, const float* __restrict__ t_gate,
                        const float* __restrict__ i_sc, const float* __restrict__ i_sh,
                        const float* __restrict__ t_sc, const float* __restrict__ t_sh,
                        float* __restrict__ resid, __nv_bfloat16* __restrict__ mih)
{
    const int row = blockIdx.x;
    const bool is_txt = row < LTXT;
    const float* e  = is_txt ? txt_e + (size_t)row * DIM : img_e + (size_t)(row - LTXT) * DIM;
    const float* g  = is_txt ? t_gate : i_gate;
    const float* sc = is_txt ? t_sc : i_sc;
    const float* sh = is_txt ? t_sh : i_sh;
    __shared__ float red[8];
    const int tid = threadIdx.x;
    float r[12];
    float s = 0.f, ss = 0.f;
    #pragma unroll
    for (int i = 0; i < 12; i++) {
        const int c = tid + i * 256;
        float x = e[c] + g[c] * proj[(size_t)row * DIM + c];
        r[i] = x; s += x; ss += x * x;
        resid[(size_t)row * DIM + c] = x;
    }
    s  = blk_sum<8>(s,  red);
    ss = blk_sum<8>(ss, red);
    const float m   = s * (1.f / DIM);
    const float var = ss * (1.f / DIM) - m * m;
    const float rs  = rsqrtf(var + 1e-6f);
    #pragma unroll
    for (int i = 0; i < 12; i++) {
        const int c = tid + i * 256;
        float y = (1.f + sc[c]) * (r[i] - m) * rs + sh[c];
        mih[(size_t)row * DIM + c] = __float2bfloat16(y);
    }
}

// ---------------- final gated residual -> d_out ----------------
__global__ __launch_bounds__(256)
void final_kernel(const float* __restrict__ mlpout, const float* __restrict__ resid,
                  const float* __restrict__ i_gate, const float* __restrict__ t_gate,
                  float* __restrict__ out)
{
    const int row = blockIdx.x;
    const int tid = threadIdx.x;
    const bool is_txt = row < LTXT;
    const float* g = is_txt ? t_gate : i_gate;
    float* dst = is_txt ? out + (size_t)LIMG * DIM + (size_t)row * DIM
                        : out + (size_t)(row - LTXT) * DIM;
    #pragma unroll
    for (int i = 0; i < 12; i++) {
        const int c = tid + i * 256;
        dst[c] = resid[(size_t)row * DIM + c] + g[c] * mlpout[(size_t)row * DIM + c];
    }
}

// ---------------- launch ----------------
extern "C" void kernel_launch(void* const* d_in, const int* in_sizes, int n_in,
                              void* d_out, int out_size)
{
    const float* img_e       = (const float*)d_in[0];
    const float* txt_e       = (const float*)d_in[1];
    const float* pe          = (const float*)d_in[2];
    const float* i_attn_sc   = (const float*)d_in[3];
    const float* i_attn_sh   = (const float*)d_in[4];
    const float* i_attn_gate = (const float*)d_in[5];
    const float* i_mlp_sc    = (const float*)d_in[6];
    const float* i_mlp_sh    = (const float*)d_in[7];
    const float* i_mlp_gate  = (const float*)d_in[8];
    const float* t_attn_sc   = (const float*)d_in[9];
    const float* t_attn_sh   = (const float*)d_in[10];
    const float* t_attn_gate = (const float*)d_in[11];
    const float* t_mlp_sc    = (const float*)d_in[12];
    const float* t_mlp_sh    = (const float*)d_in[13];
    const float* t_mlp_gate  = (const float*)d_in[14];
    const float* i_qkv_w     = (const float*)d_in[15];
    const float* i_qkv_b     = (const float*)d_in[16];
    const float* i_qknorm    = (const float*)d_in[17];
    const float* t_qkv_w     = (const float*)d_in[18];
    const float* t_qkv_b     = (const float*)d_in[19];
    const float* t_qknorm    = (const float*)d_in[20];
    const float* proj_w      = (const float*)d_in[21];
    const float* proj_b      = (const float*)d_in[22];
    const float* i_mlp_w1    = (const float*)d_in[23];
    const float* i_mlp_b1    = (const float*)d_in[24];
    const float* i_mlp_w2    = (const float*)d_in[25];
    const float* i_mlp_b2    = (const float*)d_in[26];
    const float* t_mlp_w1    = (const float*)d_in[27];
    const float* t_mlp_b1    = (const float*)d_in[28];
    const float* t_mlp_w2    = (const float*)d_in[29];
    const float* t_mlp_b2    = (const float*)d_in[30];
    // d_in[31] = mask (all-true; unused)

    __nv_bfloat16 *wh, *xmh, *qh, *kh, *vth, *ph, *ath, *mih, *mhh;
    float *qkv, *scores, *proj, *resid, *mlpout;
    cudaGetSymbolAddress((void**)&wh,     g_wh);
    cudaGetSymbolAddress((void**)&xmh,    g_xmh);
    cudaGetSymbolAddress((void**)&qkv,    g_qkv);
    cudaGetSymbolAddress((void**)&qh,     g_qh);
    cudaGetSymbolAddress((void**)&kh,     g_kh);
    cudaGetSymbolAddress((void**)&vth,    g_vth);
    cudaGetSymbolAddress((void**)&scores, g_scores);
    cudaGetSymbolAddress((void**)&ph,     g_ph);
    cudaGetSymbolAddress((void**)&ath,    g_ath);
    cudaGetSymbolAddress((void**)&proj,   g_proj);
    cudaGetSymbolAddress((void**)&resid,  g_resid);
    cudaGetSymbolAddress((void**)&mih,    g_mih);
    cudaGetSymbolAddress((void**)&mhh,    g_mhh);
    cudaGetSymbolAddress((void**)&mlpout, g_mlpout);

    const float attn_scale = 0.08838834764831845f;  // 1/sqrt(128)
    const int SMEM = 3 * 20480;                     // 61440 B
    const int BIG  = 1 << 30;

    cudaFuncSetAttribute(gemm_bf<0, 0>, cudaFuncAttributeMaxDynamicSharedMemorySize, SMEM);
    cudaFuncSetAttribute(gemm_bf<1, 0>, cudaFuncAttributeMaxDynamicSharedMemorySize, SMEM);
    cudaFuncSetAttribute(gemm_bf<1, 1>, cudaFuncAttributeMaxDynamicSharedMemorySize, SMEM);

    // 0) weight converts (hi plane only)
    wcvt_kernel<<<1024, 256>>>(t_qkv_w,  wh + W_TQKV, 3 * DIM * DIM / 4);
    wcvt_kernel<<<1024, 256>>>(i_qkv_w,  wh + W_IQKV, 3 * DIM * DIM / 4);
    wcvt_kernel<<<1024, 256>>>(proj_w,   wh + W_PROJ, DIM * DIM / 4);
    wcvt_kernel<<<1024, 256>>>(t_mlp_w1, wh + W_TW1,  MLPD * DIM / 4);
    wcvt_kernel<<<1024, 256>>>(i_mlp_w1, wh + W_IW1,  MLPD * DIM / 4);
    wcvt_kernel<<<1024, 256>>>(t_mlp_w2, wh + W_TW2,  DIM * MLPD / 4);
    wcvt_kernel<<<1024, 256>>>(i_mlp_w2, wh + W_IW2,  DIM * MLPD / 4);

    // 1) LN + attention modulation -> bf16
    lnmod_attn_kernel<<<LL, 256>>>(img_e, txt_e, i_attn_sc, i_attn_sh,
                                   t_attn_sc, t_attn_sh, xmh);

    // 2) QKV GEMM (merged txt/img via m-switch) -> fp32
    gemm_bf<0, 0><<<dim3(3 * DIM / 128, LL / 128, 1), 256, SMEM>>>(
        xmh, wh + W_TQKV, wh + W_IQKV, qkv, nullptr, t_qkv_b, i_qkv_b,
        LTXT, DIM, DIM, DIM, 3 * DIM, 0, 0, 0, 1.f);

    // 3) split + RMSNorm + RoPE -> bf16 q/k, v transposed
    qkv_post_kernel<<<dim3(LL, NH), 128>>>(qkv, pe, i_qknorm, t_qknorm, qh, kh, vth);

    // 4) scores = scale * q @ k^T -> fp32
    gemm_bf<0, 0><<<dim3(LL / 128, LL / 128, NH), 256, SMEM>>>(
        qh, kh, nullptr, scores, nullptr, nullptr, nullptr,
        BIG, DH, DH, DH, LL,
        (long long)LL * DH, (long long)LL * DH, (long long)LL * LL, attn_scale);

    // 5) softmax -> bf16 p
    softmax_kernel<<<NH * LL, 256>>>(scores, ph);

    // 6) o = p @ v^T -> bf16 attn (OUT=1)
    gemm_bf<1, 0><<<dim3(1, LL / 128, NH), 256, SMEM>>>(
        ph, vth, nullptr, nullptr, ath, nullptr, nullptr,
        BIG, LL, LL, LL, DIM,
        (long long)LL * LL, (long long)DH * LL, (long long)DH, 1.f);

    // 7) shared projection -> fp32
    gemm_bf<0, 0><<<dim3(DIM / 128, LL / 128, 1), 256, SMEM>>>(
        ath, wh + W_PROJ, nullptr, proj, nullptr, proj_b, nullptr,
        BIG, DIM, DIM, DIM, DIM, 0, 0, 0, 1.f);

    // 8) gated attn residual + LN + MLP modulation
    resid_lnmod_kernel<<<LL, 256>>>(proj, img_e, txt_e,
                                    i_attn_gate, t_attn_gate,
                                    i_mlp_sc, i_mlp_sh, t_mlp_sc, t_mlp_sh,
                                    resid, mih);

    // 9) MLP up (merged, bias+gelu fused) -> bf16 h
    gemm_bf<1, 1><<<dim3(MLPD / 128, LL / 128, 1), 256, SMEM>>>(
        mih, wh + W_TW1, wh + W_IW1, nullptr, mhh, t_mlp_b1, i_mlp_b1,
        LTXT, DIM, DIM, DIM, MLPD, 0, 0, 0, 1.f);

    // 10) MLP down (merged) -> fp32
    gemm_bf<0, 0><<<dim3(DIM / 128, LL / 128, 1), 256, SMEM>>>(
        mhh, wh + W_TW2, wh + W_IW2, mlpout, nullptr, t_mlp_b2, i_mlp_b2,
        LTXT, MLPD, MLPD, MLPD, DIM, 0, 0, 0, 1.f);

    // 11) final gated residual -> output (img block first, then txt block)
    final_kernel<<<LL, 256>>>(mlpout, resid, i_mlp_gate, t_mlp_gate, (float*)d_out);
}

// round 9
// speedup vs baseline: 8.2919x; 1.2715x over previous
#include <cuda_runtime.h>
#include <cuda_bf16.h>
#include <stdint.h>
#include <math.h>

// ---------------- problem constants ----------------
#define LL    2048
#define LTXT  512
#define LIMG  1536
#define DIM   3072
#define NH    24
#define DH    128
#define MLPD  12288

// ---------------- scratch ----------------
__device__ __nv_bfloat16 g_xmh[(size_t)LL * DIM];
__device__ float         g_qkv[(size_t)LL * 3 * DIM];
__device__ __nv_bfloat16 g_qh [(size_t)NH * LL * DH];
__device__ __nv_bfloat16 g_kh [(size_t)NH * LL * DH];
__device__ __nv_bfloat16 g_vth[(size_t)NH * DH * LL];   // [h][dh][l]
__device__ __nv_bfloat16 g_ath[(size_t)LL * DIM];
__device__ float         g_part[(size_t)4 * LL * DIM];  // split-K partials
__device__ float         g_resid[(size_t)LL * DIM];
__device__ __nv_bfloat16 g_mih[(size_t)LL * DIM];
__device__ __nv_bfloat16 g_mhh[(size_t)LL * MLPD];

// ---------------- helpers ----------------
template<int NW>
__device__ __forceinline__ float blk_sum(float v, float* sh) {
    #pragma unroll
    for (int o = 16; o; o >>= 1) v += __shfl_down_sync(0xffffffffu, v, o);
    int lane = threadIdx.x & 31, w = threadIdx.x >> 5;
    if (lane == 0) sh[w] = v;
    __syncthreads();
    if (threadIdx.x == 0) {
        float r = 0.f;
        #pragma unroll
        for (int i = 0; i < NW; i++) r += sh[i];
        sh[0] = r;
    }
    __syncthreads();
    float r = sh[0];
    __syncthreads();
    return r;
}

__device__ __forceinline__ void mma_bf16(float d[4], const uint32_t a[4],
                                         const uint32_t b[2]) {
    asm volatile(
        "mma.sync.aligned.m16n8k16.row.col.f32.bf16.bf16.f32 "
        "{%0,%1,%2,%3},{%4,%5,%6,%7},{%8,%9},{%0,%1,%2,%3};"
        : "+f"(d[0]), "+f"(d[1]), "+f"(d[2]), "+f"(d[3])
        : "r"(a[0]), "r"(a[1]), "r"(a[2]), "r"(a[3]), "r"(b[0]), "r"(b[1]));
}

__device__ __forceinline__ void ldsm4(uint32_t r[4], uint32_t addr) {
    asm volatile("ldmatrix.sync.aligned.m8n8.x4.shared.b16 {%0,%1,%2,%3}, [%4];"
                 : "=r"(r[0]), "=r"(r[1]), "=r"(r[2]), "=r"(r[3]) : "r"(addr));
}

__device__ __forceinline__ void cpa(uint32_t d, const void* s) {
    asm volatile("cp.async.cg.shared.global [%0], [%1], 16;" :: "r"(d), "l"(s));
}

__device__ __forceinline__ float ex2(float x) {
    float y;
    asm("ex2.approx.ftz.f32 %0, %1;" : "=f"(y) : "f"(x));
    return y;
}

__device__ __forceinline__ uint32_t packbf(float a, float b) {
    __nv_bfloat162 t(__float2bfloat16(a), __float2bfloat16(b));
    return *reinterpret_cast<uint32_t*>(&t);
}

// ================= GEMM: C = alpha * A(bf16) @ B(fp32 wt)^T (+bias)(+gelu) ====
// A [M,K] bf16 (cp.async, 3-stage). B [N,K] fp32, converted in-loop (reg-buffered,
// 2-stage). OUT: 0 fp32 C; 1 bf16 Ch. Blocks with m0>=mswitch use Bw2/bias2.
// Split-K via blockIdx.z: A/B advance sA/sB elems, C advances sC.
// smem: A stages @0,10240,20480; B stages @30720,40960. Total 51200 B.
__device__ __forceinline__ void compute_tile_ws(uint32_t sA_, uint32_t sB_,
                                                int wm, int wn, int lane,
                                                float acc[4][4][4])
{
    const int aRow = lane & 15;
    const int aK   = (lane & 16) ? 8 : 0;
    const int bRow = (lane & 7) + ((lane & 16) ? 8 : 0);
    const int bK   = (lane & 8) ? 8 : 0;
    #pragma unroll
    for (int kh = 0; kh < 32; kh += 16) {
        uint32_t ah[4][4];
        uint32_t bh[2][4];
        #pragma unroll
        for (int mt = 0; mt < 4; mt++) {
            uint32_t off = (uint32_t)((wm + mt * 16 + aRow) * 40 + kh + aK) * 2u;
            ldsm4(ah[mt], sA_ + off);
        }
        #pragma unroll
        for (int pr = 0; pr < 2; pr++) {
            uint32_t off = (uint32_t)((wn + pr * 16 + bRow) * 40 + kh + bK) * 2u;
            ldsm4(bh[pr], sB_ + off);
        }
        #pragma unroll
        for (int mt = 0; mt < 4; mt++)
            #pragma unroll
            for (int nt = 0; nt < 4; nt++)
                mma_bf16(acc[mt][nt], ah[mt], &bh[nt >> 1][(nt & 1) * 2]);
    }
}

template<int OUT, int ACT>
__global__ __launch_bounds__(256, 2)
void gemm_wf(const __nv_bfloat16* __restrict__ Ah,
             const float* __restrict__ Bw, const float* __restrict__ Bw2,
             float* __restrict__ C, __nv_bfloat16* __restrict__ Ch,
             const float* __restrict__ bias, const float* __restrict__ bias2,
             int mswitch, int K, int lda, int ldb, int ldc,
             long long sA, long long sB, long long sC, float alpha)
{
    extern __shared__ __align__(128) char smem[];
    const int tid = threadIdx.x;
    const int lane = tid & 31;
    const int warp = tid >> 5;
    const int wm = (warp >> 2) * 64;
    const int wn = (warp & 3) * 32;

    const int m0 = blockIdx.y * 128;
    const int n0 = blockIdx.x * 128;

    const float* Bsel = Bw;
    if (Bw2 && m0 >= mswitch) { Bsel = Bw2; bias = bias2; }
    Ah   += sA * blockIdx.z;
    Bsel += sB * blockIdx.z;
    if (OUT == 0) C  += sC * blockIdx.z;
    else          Ch += sC * blockIdx.z;

    const uint32_t sbase = (uint32_t)__cvta_generic_to_shared(smem);

    float acc[4][4][4];
    #pragma unroll
    for (int i = 0; i < 4; i++)
        #pragma unroll
        for (int j = 0; j < 4; j++) {
            acc[i][j][0] = 0.f; acc[i][j][1] = 0.f;
            acc[i][j][2] = 0.f; acc[i][j][3] = 0.f;
        }

    const int NC = K >> 5;   // KT=32; NC >= 2 for all uses
    float4 rb[4];

    // prologue: A chunks 0,1 via cp.async
    #pragma unroll
    for (int p = 0; p < 2; p++) {
        #pragma unroll
        for (int i = 0; i < 2; i++) {
            int s = tid + i * 256;
            int row = s >> 2, cc = (s & 3) << 3;
            cpa(sbase + (uint32_t)p * 10240u + (uint32_t)(row * 40 + cc) * 2u,
                &Ah[(long long)(m0 + row) * lda + p * 32 + cc]);
        }
        asm volatile("cp.async.commit_group;" ::: "memory");
    }
    // B chunk 0 -> regs -> smem stage 0
    #pragma unroll
    for (int i = 0; i < 4; i++) {
        int s = tid + i * 256;
        int row = s >> 3, cc = (s & 7) << 2;
        rb[i] = *reinterpret_cast<const float4*>(&Bsel[(long long)(n0 + row) * ldb + cc]);
    }
    #pragma unroll
    for (int i = 0; i < 4; i++) {
        int s = tid + i * 256;
        int row = s >> 3, cc = (s & 7) << 2;
        uint2 pk;
        pk.x = packbf(rb[i].x, rb[i].y);
        pk.y = packbf(rb[i].z, rb[i].w);
        *reinterpret_cast<uint2*>(smem + 30720 + (row * 40 + cc) * 2) = pk;
    }
    // prefetch B chunk 1 into regs
    if (NC > 1) {
        #pragma unroll
        for (int i = 0; i < 4; i++) {
            int s = tid + i * 256;
            int row = s >> 3, cc = (s & 7) << 2;
            rb[i] = *reinterpret_cast<const float4*>(
                &Bsel[(long long)(n0 + row) * ldb + 32 + cc]);
        }
    }
    asm volatile("cp.async.wait_group 1;" ::: "memory");
    __syncthreads();

    for (int c = 0; c < NC; c++) {
        if (c + 2 < NC) {
            const int cc2 = c + 2;
            #pragma unroll
            for (int i = 0; i < 2; i++) {
                int s = tid + i * 256;
                int row = s >> 2, ccx = (s & 3) << 3;
                cpa(sbase + (uint32_t)(cc2 % 3) * 10240u
                        + (uint32_t)(row * 40 + ccx) * 2u,
                    &Ah[(long long)(m0 + row) * lda + cc2 * 32 + ccx]);
            }
        }
        asm volatile("cp.async.commit_group;" ::: "memory");

        compute_tile_ws(sbase + (uint32_t)(c % 3) * 10240u,
                        sbase + 30720u + (uint32_t)(c & 1) * 10240u,
                        wm, wn, lane, acc);
        __syncthreads();

        if (c + 1 < NC) {
            #pragma unroll
            for (int i = 0; i < 4; i++) {
                int s = tid + i * 256;
                int row = s >> 3, cc = (s & 7) << 2;
                uint2 pk;
                pk.x = packbf(rb[i].x, rb[i].y);
                pk.y = packbf(rb[i].z, rb[i].w);
                *reinterpret_cast<uint2*>(
                    smem + 30720 + ((c + 1) & 1) * 10240 + (row * 40 + cc) * 2) = pk;
            }
            if (c + 2 < NC) {
                #pragma unroll
                for (int i = 0; i < 4; i++) {
                    int s = tid + i * 256;
                    int row = s >> 3, cc = (s & 7) << 2;
                    rb[i] = *reinterpret_cast<const float4*>(
                        &Bsel[(long long)(n0 + row) * ldb + (c + 2) * 32 + cc]);
                }
            }
            asm volatile("cp.async.wait_group 1;" ::: "memory");
            __syncthreads();
        }
    }

    // epilogue
    const int crow = lane >> 2;
    const int ccol = (lane & 3) << 1;
    #pragma unroll
    for (int mt = 0; mt < 4; mt++) {
        #pragma unroll
        for (int nt = 0; nt < 4; nt++) {
            const int gn = n0 + wn + nt * 8 + ccol;
            #pragma unroll
            for (int half = 0; half < 2; half++) {
                const int gm = m0 + wm + mt * 16 + crow + half * 8;
                float v0 = acc[mt][nt][half * 2 + 0] * alpha;
                float v1 = acc[mt][nt][half * 2 + 1] * alpha;
                if (bias) { v0 += bias[gn]; v1 += bias[gn + 1]; }
                if (ACT == 1) {
                    float x = v0;
                    v0 = 0.5f * x * (1.f + tanhf(0.7978845608028654f *
                                                 (x + 0.044715f * x * x * x)));
                    x = v1;
                    v1 = 0.5f * x * (1.f + tanhf(0.7978845608028654f *
                                                 (x + 0.044715f * x * x * x)));
                }
                const long long ci = (long long)gm * ldc + gn;
                if (OUT == 0) {
                    *reinterpret_cast<float2*>(&C[ci]) = make_float2(v0, v1);
                } else {
                    *reinterpret_cast<__nv_bfloat162*>(&Ch[ci]) =
                        __nv_bfloat162(__float2bfloat16(v0), __float2bfloat16(v1));
                }
            }
        }
    }
}

// ================= flash attention ==========================================
// grid (LL/64, NH), 128 threads. q-tile 64x128; kv blocks of 128; online softmax.
// smem: q[64][136] @0 (17408), k[128][136] @17408, v[128][136] @52224. 87040 B.
// NOTE: rows are 256B (128 bf16); 16 x 16B chunks per row.
__global__ __launch_bounds__(128, 2)
void flash_kernel(const __nv_bfloat16* __restrict__ qg_,
                  const __nv_bfloat16* __restrict__ kg_,
                  const __nv_bfloat16* __restrict__ vg_,
                  __nv_bfloat16* __restrict__ o_)
{
    extern __shared__ __align__(128) char fsm[];
    const int tid = threadIdx.x, lane = tid & 31, warp = tid >> 5;
    const int qb = blockIdx.x, h = blockIdx.y;
    const char* qg = (const char*)(qg_ + ((size_t)h * LL + (size_t)qb * 64) * DH);
    const char* kg = (const char*)(kg_ + (size_t)h * LL * DH);
    const char* vg = (const char*)(vg_ + (size_t)h * DH * LL);
    const uint32_t sq = (uint32_t)__cvta_generic_to_shared(fsm);
    const uint32_t sk = sq + 17408u;
    const uint32_t sv = sq + 52224u;

    const int aRow = lane & 15;
    const int aK   = (lane & 16) ? 8 : 0;
    const int bRow = (lane & 7) + ((lane & 16) ? 8 : 0);
    const int bK   = (lane & 8) ? 8 : 0;
    const int g = lane >> 2, t4 = lane & 3;

    // load q tile: 64 rows x 256B = 1024 x 16B chunks
    #pragma unroll
    for (int i = 0; i < 8; i++) {
        int idx = tid + i * 128;
        int row = idx >> 4, cb = (idx & 15) * 16;
        cpa(sq + (uint32_t)(row * 272 + cb), qg + row * 256 + cb);
    }
    asm volatile("cp.async.commit_group;" ::: "memory");

    float mv0 = -1e30f, mv1 = -1e30f, l0 = 0.f, l1 = 0.f;
    float oa[16][4];
    #pragma unroll
    for (int nt = 0; nt < 16; nt++) {
        oa[nt][0] = 0.f; oa[nt][1] = 0.f; oa[nt][2] = 0.f; oa[nt][3] = 0.f;
    }

    const float Cc = 0.12751781429348323f;  // (1/sqrt(128)) * log2(e)

    for (int kb = 0; kb < 16; kb++) {
        __syncthreads();   // previous block's smem reads done
        // k/v tiles: 128 rows x 256B = 2048 x 16B chunks each
        #pragma unroll
        for (int i = 0; i < 16; i++) {
            int idx = tid + i * 128;
            int row = idx >> 4, cb = (idx & 15) * 16;
            cpa(sk + (uint32_t)(row * 272 + cb),
                kg + (size_t)(kb * 128 + row) * 256 + cb);
            cpa(sv + (uint32_t)(row * 272 + cb),
                vg + (size_t)row * 4096 + kb * 256 + cb);
        }
        asm volatile("cp.async.commit_group;" ::: "memory");
        asm volatile("cp.async.wait_group 0;" ::: "memory");
        __syncthreads();

        // S = q @ k^T (64x128 per CTA, 16x128 per warp)
        float sa[16][4];
        #pragma unroll
        for (int nt = 0; nt < 16; nt++) {
            sa[nt][0] = 0.f; sa[nt][1] = 0.f; sa[nt][2] = 0.f; sa[nt][3] = 0.f;
        }
        #pragma unroll
        for (int ks = 0; ks < 8; ks++) {
            uint32_t qf[4];
            ldsm4(qf, sq + (uint32_t)((warp * 16 + aRow) * 136 + ks * 16 + aK) * 2u);
            #pragma unroll
            for (int pr = 0; pr < 8; pr++) {
                uint32_t bf[4];
                ldsm4(bf, sk + (uint32_t)((pr * 16 + bRow) * 136 + ks * 16 + bK) * 2u);
                mma_bf16(sa[2 * pr],     qf, &bf[0]);
                mma_bf16(sa[2 * pr + 1], qf, &bf[2]);
            }
        }

        // row stats (rows g and g+8 of this warp's 16)
        float rm0 = -1e30f, rm1 = -1e30f;
        #pragma unroll
        for (int nt = 0; nt < 16; nt++) {
            rm0 = fmaxf(rm0, fmaxf(sa[nt][0], sa[nt][1]));
            rm1 = fmaxf(rm1, fmaxf(sa[nt][2], sa[nt][3]));
        }
        rm0 = fmaxf(rm0, __shfl_xor_sync(0xffffffffu, rm0, 1));
        rm0 = fmaxf(rm0, __shfl_xor_sync(0xffffffffu, rm0, 2));
        rm1 = fmaxf(rm1, __shfl_xor_sync(0xffffffffu, rm1, 1));
        rm1 = fmaxf(rm1, __shfl_xor_sync(0xffffffffu, rm1, 2));
        const float mn0 = fmaxf(mv0, rm0), mn1 = fmaxf(mv1, rm1);
        const float r0 = ex2((mv0 - mn0) * Cc), r1 = ex2((mv1 - mn1) * Cc);
        mv0 = mn0; mv1 = mn1;

        float s0 = 0.f, s1 = 0.f;
        uint32_t pf[16], pg[16];
        #pragma unroll
        for (int nt = 0; nt < 16; nt++) {
            float p0 = ex2((sa[nt][0] - mn0) * Cc);
            float p1 = ex2((sa[nt][1] - mn0) * Cc);
            float p2 = ex2((sa[nt][2] - mn1) * Cc);
            float p3 = ex2((sa[nt][3] - mn1) * Cc);
            s0 += p0 + p1; s1 += p2 + p3;
            pf[nt] = packbf(p0, p1);
            pg[nt] = packbf(p2, p3);
        }
        s0 += __shfl_xor_sync(0xffffffffu, s0, 1);
        s0 += __shfl_xor_sync(0xffffffffu, s0, 2);
        s1 += __shfl_xor_sync(0xffffffffu, s1, 1);
        s1 += __shfl_xor_sync(0xffffffffu, s1, 2);
        l0 = l0 * r0 + s0;
        l1 = l1 * r1 + s1;
        #pragma unroll
        for (int nt = 0; nt < 16; nt++) {
            oa[nt][0] *= r0; oa[nt][1] *= r0;
            oa[nt][2] *= r1; oa[nt][3] *= r1;
        }

        // o += p @ v   (A from registers, B = v[dh][kv] from smem)
        #pragma unroll
        for (int ks = 0; ks < 8; ks++) {
            uint32_t af[4];
            af[0] = pf[2 * ks];     af[1] = pg[2 * ks];
            af[2] = pf[2 * ks + 1]; af[3] = pg[2 * ks + 1];
            #pragma unroll
            for (int pr = 0; pr < 8; pr++) {
                uint32_t bf[4];
                ldsm4(bf, sv + (uint32_t)((pr * 16 + bRow) * 136 + ks * 16 + bK) * 2u);
                mma_bf16(oa[2 * pr],     af, &bf[0]);
                mma_bf16(oa[2 * pr + 1], af, &bf[2]);
            }
        }
    }

    // epilogue: o /= l, write bf16 to [l, h*DH + dh]
    const float i0 = 1.f / l0, i1 = 1.f / l1;
    const int row0 = qb * 64 + warp * 16 + g;
    #pragma unroll
    for (int nt = 0; nt < 16; nt++) {
        const int col = h * DH + nt * 8 + 2 * t4;
        *reinterpret_cast<__nv_bfloat162*>(&o_[(size_t)row0 * DIM + col]) =
            __nv_bfloat162(__float2bfloat16(oa[nt][0] * i0),
                           __float2bfloat16(oa[nt][1] * i0));
        *reinterpret_cast<__nv_bfloat162*>(&o_[(size_t)(row0 + 8) * DIM + col]) =
            __nv_bfloat162(__float2bfloat16(oa[nt][2] * i1),
                           __float2bfloat16(oa[nt][3] * i1));
    }
}

// ---------------- LN + adaLN modulation -> bf16 ----------------
__global__ __launch_bounds__(256)
void lnmod_attn_kernel(const float* __restrict__ img_e, const float* __restrict__ txt_e,
                       const float* __restrict__ i_sc, const float* __restrict__ i_sh,
                       const float* __restrict__ t_sc, const float* __restrict__ t_sh,
                       __nv_bfloat16* __restrict__ oh)
{
    const int row = blockIdx.x;
    const bool is_txt = row < LTXT;
    const float* x  = is_txt ? txt_e + (size_t)row * DIM : img_e + (size_t)(row - LTXT) * DIM;
    const float* sc = is_txt ? t_sc : i_sc;
    const float* sh = is_txt ? t_sh : i_sh;
    __shared__ float red[8];
    const int tid = threadIdx.x;
    float v[12];
    float s = 0.f, ss = 0.f;
    #pragma unroll
    for (int i = 0; i < 12; i++) {
        float a = x[tid + i * 256];
        v[i] = a; s += a; ss += a * a;
    }
    s  = blk_sum<8>(s,  red);
    ss = blk_sum<8>(ss, red);
    const float m   = s * (1.f / DIM);
    const float var = ss * (1.f / DIM) - m * m;
    const float rs  = rsqrtf(var + 1e-6f);
    #pragma unroll
    for (int i = 0; i < 12; i++) {
        const int c = tid + i * 256;
        oh[(size_t)row * DIM + c] =
            __float2bfloat16((1.f + sc[c]) * (v[i] - m) * rs + sh[c]);
    }
}

// ---------------- qkv split + RMSNorm(q,k) + RoPE -> bf16 ----------
__global__ __launch_bounds__(128)
void qkv_post_kernel(const float* __restrict__ qkv, const float* __restrict__ pe,
                     const float* __restrict__ img_w, const float* __restrict__ txt_w,
                     __nv_bfloat16* __restrict__ qh, __nv_bfloat16* __restrict__ kh,
                     __nv_bfloat16* __restrict__ vth)
{
    const int row = blockIdx.x;
    const int h   = blockIdx.y;
    const int d   = threadIdx.x;
    const float* w = (row < LTXT) ? txt_w : img_w;

    const size_t base = (size_t)row * (3 * DIM) + (size_t)h * DH + d;
    const float qv = qkv[base];
    const float kv = qkv[base + DIM];
    const float vv = qkv[base + 2 * DIM];

    __shared__ float shq[4], shk[4], bc[2];
    __shared__ float qn[DH], kn[DH];

    float qs = qv * qv, ks = kv * kv;
    #pragma unroll
    for (int o = 16; o; o >>= 1) {
        qs += __shfl_down_sync(0xffffffffu, qs, o);
        ks += __shfl_down_sync(0xffffffffu, ks, o);
    }
    const int lane = d & 31, wp = d >> 5;
    if (lane == 0) { shq[wp] = qs; shk[wp] = ks; }
    __syncthreads();
    if (d == 0) bc[0] = rsqrtf((shq[0] + shq[1] + shq[2] + shq[3]) * (1.f / DH) + 1e-6f);
    if (d == 1) bc[1] = rsqrtf((shk[0] + shk[1] + shk[2] + shk[3]) * (1.f / DH) + 1e-6f);
    __syncthreads();

    qn[d] = qv * bc[0] * w[d];
    kn[d] = kv * bc[1] * w[d];
    __syncthreads();

    const int d2 = d >> 1;
    const float c = pe[(size_t)row * 256 + d2 * 4 + 0];
    const float s = pe[(size_t)row * 256 + d2 * 4 + 2];
    const float qr = qn[d2 * 2], qi = qn[d2 * 2 + 1];
    const float kr = kn[d2 * 2], ki = kn[d2 * 2 + 1];
    const float qo = (d & 1) ? (qr * s + qi * c) : (qr * c - qi * s);
    const float ko = (d & 1) ? (kr * s + ki * c) : (kr * c - ki * s);

    const size_t o = ((size_t)h * LL + row) * DH + d;
    qh[o] = __float2bfloat16(qo);
    kh[o] = __float2bfloat16(ko);
    vth[((size_t)h * DH + d) * LL + row] = __float2bfloat16(vv);
}

// ---- attn residual (gated, 4-way split-K reduce + bias) + LN + MLP mod ----
__global__ __launch_bounds__(256)
void resid_lnmod_kernel(const float* __restrict__ part, const float* __restrict__ proj_b,
                        const float* __restrict__ img_e, const float* __restrict__ txt_e,
                        const float* __restrict__ i_gate, const float* __restrict__ t_gate,
                        const float* __restrict__ i_sc, const float* __restrict__ i_sh,
                        const float* __restrict__ t_sc, const float* __restrict__ t_sh,
                        float* __restrict__ resid, __nv_bfloat16* __restrict__ mih)
{
    const int row = blockIdx.x;
    const bool is_txt = row < LTXT;
    const float* e  = is_txt ? txt_e + (size_t)row * DIM : img_e + (size_t)(row - LTXT) * DIM;
    const float* g  = is_txt ? t_gate : i_gate;
    const float* sc = is_txt ? t_sc : i_sc;
    const float* sh = is_txt ? t_sh : i_sh;
    __shared__ float red[8];
    const int tid = threadIdx.x;
    const size_t PS = (size_t)LL * DIM;
    float r[12];
    float s = 0.f, ss = 0.f;
    #pragma unroll
    for (int i = 0; i < 12; i++) {
        const int c = tid + i * 256;
        const size_t idx = (size_t)row * DIM + c;
        float p = part[idx] + part[PS + idx] + part[2 * PS + idx] + part[3 * PS + idx]
                + proj_b[c];
        float x = e[c] + g[c] * p;
        r[i] = x; s += x; ss += x * x;
        resid[idx] = x;
    }
    s  = blk_sum<8>(s,  red);
    ss = blk_sum<8>(ss, red);
    const float m   = s * (1.f / DIM);
    const float var = ss * (1.f / DIM) - m * m;
    const float rs  = rsqrtf(var + 1e-6f);
    #pragma unroll
    for (int i = 0; i < 12; i++) {
        const int c = tid + i * 256;
        mih[(size_t)row * DIM + c] =
            __float2bfloat16((1.f + sc[c]) * (r[i] - m) * rs + sh[c]);
    }
}

// ---- final gated residual (4-way split-K reduce + bias) -> d_out ----
__global__ __launch_bounds__(256)
void final_kernel(const float* __restrict__ part,
                  const float* __restrict__ t_b2, const float* __restrict__ i_b2,
                  const float* __restrict__ resid,
                  const float* __restrict__ i_gate, const float* __restrict__ t_gate,
                  float* __restrict__ out)
{
    const int row = blockIdx.x;
    const int tid = threadIdx.x;
    const bool is_txt = row < LTXT;
    const float* g  = is_txt ? t_gate : i_gate;
    const float* b2 = is_txt ? t_b2 : i_b2;
    const size_t PS = (size_t)LL * DIM;
    float* dst = is_txt ? out + (size_t)LIMG * DIM + (size_t)row * DIM
                        : out + (size_t)(row - LTXT) * DIM;
    #pragma unroll
    for (int i = 0; i < 12; i++) {
        const int c = tid + i * 256;
        const size_t idx = (size_t)row * DIM + c;
        float mlp = part[idx] + part[PS + idx] + part[2 * PS + idx]
                  + part[3 * PS + idx] + b2[c];
        dst[c] = resid[idx] + g[c] * mlp;
    }
}

// ---------------- launch ----------------
extern "C" void kernel_launch(void* const* d_in, const int* in_sizes, int n_in,
                              void* d_out, int out_size)
{
    const float* img_e       = (const float*)d_in[0];
    const float* txt_e       = (const float*)d_in[1];
    const float* pe          = (const float*)d_in[2];
    const float* i_attn_sc   = (const float*)d_in[3];
    const float* i_attn_sh   = (const float*)d_in[4];
    const float* i_attn_gate = (const float*)d_in[5];
    const float* i_mlp_sc    = (const float*)d_in[6];
    const float* i_mlp_sh    = (const float*)d_in[7];
    const float* i_mlp_gate  = (const float*)d_in[8];
    const float* t_attn_sc   = (const float*)d_in[9];
    const float* t_attn_sh   = (const float*)d_in[10];
    const float* t_attn_gate = (const float*)d_in[11];
    const float* t_mlp_sc    = (const float*)d_in[12];
    const float* t_mlp_sh    = (const float*)d_in[13];
    const float* t_mlp_gate  = (const float*)d_in[14];
    const float* i_qkv_w     = (const float*)d_in[15];
    const float* i_qkv_b     = (const float*)d_in[16];
    const float* i_qknorm    = (const float*)d_in[17];
    const float* t_qkv_w     = (const float*)d_in[18];
    const float* t_qkv_b     = (const float*)d_in[19];
    const float* t_qknorm    = (const float*)d_in[20];
    const float* proj_w      = (const float*)d_in[21];
    const float* proj_b      = (const float*)d_in[22];
    const float* i_mlp_w1    = (const float*)d_in[23];
    const float* i_mlp_b1    = (const float*)d_in[24];
    const float* i_mlp_w2    = (const float*)d_in[25];
    const float* i_mlp_b2    = (const float*)d_in[26];
    const float* t_mlp_w1    = (const float*)d_in[27];
    const float* t_mlp_b1    = (const float*)d_in[28];
    const float* t_mlp_w2    = (const float*)d_in[29];
    const float* t_mlp_b2    = (const float*)d_in[30];
    // d_in[31] = mask (all-true; unused)

    __nv_bfloat16 *xmh, *qh, *kh, *vth, *ath, *mih, *mhh;
    float *qkv, *part, *resid;
    cudaGetSymbolAddress((void**)&xmh,   g_xmh);
    cudaGetSymbolAddress((void**)&qkv,   g_qkv);
    cudaGetSymbolAddress((void**)&qh,    g_qh);
    cudaGetSymbolAddress((void**)&kh,    g_kh);
    cudaGetSymbolAddress((void**)&vth,   g_vth);
    cudaGetSymbolAddress((void**)&ath,   g_ath);
    cudaGetSymbolAddress((void**)&part,  g_part);
    cudaGetSymbolAddress((void**)&resid, g_resid);
    cudaGetSymbolAddress((void**)&mih,   g_mih);
    cudaGetSymbolAddress((void**)&mhh,   g_mhh);

    const int GSMEM = 51200;
    const int FSMEM = 87040;
    cudaFuncSetAttribute(gemm_wf<0, 0>, cudaFuncAttributeMaxDynamicSharedMemorySize, GSMEM);
    cudaFuncSetAttribute(gemm_wf<1, 1>, cudaFuncAttributeMaxDynamicSharedMemorySize, GSMEM);
    cudaFuncSetAttribute(flash_kernel,  cudaFuncAttributeMaxDynamicSharedMemorySize, FSMEM);

    // 1) LN + attention modulation -> bf16
    lnmod_attn_kernel<<<LL, 256>>>(img_e, txt_e, i_attn_sc, i_attn_sh,
                                   t_attn_sc, t_attn_sh, xmh);

    // 2) QKV GEMM (merged txt/img, inline weight conversion) -> fp32
    gemm_wf<0, 0><<<dim3(3 * DIM / 128, LL / 128, 1), 256, GSMEM>>>(
        xmh, t_qkv_w, i_qkv_w, qkv, nullptr, t_qkv_b, i_qkv_b,
        LTXT, DIM, DIM, DIM, 3 * DIM, 0, 0, 0, 1.f);

    // 3) split + RMSNorm + RoPE -> bf16 q/k, v transposed
    qkv_post_kernel<<<dim3(LL, NH), 128>>>(qkv, pe, i_qknorm, t_qknorm, qh, kh, vth);

    // 4) fused flash attention -> bf16 ath [l, h*DH+dh]
    flash_kernel<<<dim3(LL / 64, NH), 128, FSMEM>>>(qh, kh, vth, ath);

    // 5) shared projection, split-K=4 -> fp32 partials
    gemm_wf<0, 0><<<dim3(DIM / 128, LL / 128, 4), 256, GSMEM>>>(
        ath, proj_w, nullptr, part, nullptr, nullptr, nullptr,
        0, DIM / 4, DIM, DIM, DIM,
        (long long)(DIM / 4), (long long)(DIM / 4), (long long)LL * DIM, 1.f);

    // 6) gated attn residual (reduce partials + bias) + LN + MLP modulation
    resid_lnmod_kernel<<<LL, 256>>>(part, proj_b, img_e, txt_e,
                                    i_attn_gate, t_attn_gate,
                                    i_mlp_sc, i_mlp_sh, t_mlp_sc, t_mlp_sh,
                                    resid, mih);

    // 7) MLP up (merged, bias+gelu fused) -> bf16 h
    gemm_wf<1, 1><<<dim3(MLPD / 128, LL / 128, 1), 256, GSMEM>>>(
        mih, t_mlp_w1, i_mlp_w1, nullptr, mhh, t_mlp_b1, i_mlp_b1,
        LTXT, DIM, DIM, DIM, MLPD, 0, 0, 0, 1.f);

    // 8) MLP down (merged, split-K=4) -> fp32 partials
    gemm_wf<0, 0><<<dim3(DIM / 128, LL / 128, 4), 256, GSMEM>>>(
        mhh, t_mlp_w2, i_mlp_w2, part, nullptr, nullptr, nullptr,
        LTXT, MLPD / 4, MLPD, MLPD, DIM,
        (long long)(MLPD / 4), (long long)(MLPD / 4), (long long)LL * DIM, 1.f);

    // 9) final gated residual (reduce partials + bias) -> output
    final_kernel<<<LL, 256>>>(part, t_mlp_b2, i_mlp_b2, resid,
                              i_mlp_gate, t_mlp_gate, (float*)d_out);
}